// round 4
// baseline (speedup 1.0000x reference)
#include <cuda_runtime.h>
#include <cuda_fp16.h>

#define NV   120000
#define ND   30000
#define NV2  60000
#define NPTS 400000
#define CD   128
#define HD   64

// ---------------- scratch (static device globals; no allocation) ----------------
__device__ float  g_ds[ND * CD];          // segment sums of x
__device__ float  g_cntd[ND];
__device__ __half g_idh[NV * CD];         // identity, f16
__device__ float  g_t1[ND * HD];
__device__ float  g_t2[ND * HD];
__device__ __half g_hmh[ND * CD];         // hm, f16
__device__ float  g_pfea[NV2 * CD];       // segment sums of pts
__device__ float  g_cntv2[NV2];
__device__ float  g_stats[512];
// fragment-layout weights: idx = ((c*4 + wn)*32 + lane)*8 + nf*2 + j
__device__ __align__(16) unsigned g_Wof1[16 * 4 * 32 * 8];   // Wo1 (K=256): 64KB
__device__ __align__(16) unsigned g_Wof2[8 * 4 * 32 * 8];    // Wo2 (K=128): 32KB
__device__ __align__(16) unsigned g_Wofin[8 * 4 * 32 * 8];   // W_in (K=128): 32KB

__device__ __forceinline__ float lrelu(float x) { return x > 0.f ? x : 0.1f * x; }

__device__ __forceinline__ void red_add_v4(float* p, float4 v) {
    asm volatile("red.global.add.v4.f32 [%0], {%1,%2,%3,%4};"
                 :: "l"(p), "f"(v.x), "f"(v.y), "f"(v.z), "f"(v.w) : "memory");
}
__device__ __forceinline__ void red_add_v2(float* p, float a, float b) {
    asm volatile("red.global.add.v2.f32 [%0], {%1,%2};"
                 :: "l"(p), "f"(a), "f"(b) : "memory");
}
__device__ __forceinline__ void mma16816(float* c, const unsigned* a, const unsigned* b) {
    asm volatile("mma.sync.aligned.m16n8k16.row.col.f32.f16.f16.f32 "
                 "{%0,%1,%2,%3},{%4,%5,%6,%7},{%8,%9},{%0,%1,%2,%3};"
                 : "+f"(c[0]), "+f"(c[1]), "+f"(c[2]), "+f"(c[3])
                 : "r"(a[0]), "r"(a[1]), "r"(a[2]), "r"(a[3]), "r"(b[0]), "r"(b[1]));
}

// ---------------- zero scratch ----------------
__global__ void k_zero() {
    int idx = blockIdx.x * blockDim.x + threadIdx.x;
    int stride = gridDim.x * blockDim.x;
    for (int i = idx; i < ND * CD; i += stride)  g_ds[i] = 0.f;
    for (int i = idx; i < ND; i += stride)       g_cntd[i] = 0.f;
    for (int i = idx; i < NV2 * CD; i += stride) g_pfea[i] = 0.f;
    for (int i = idx; i < NV2; i += stride)      g_cntv2[i] = 0.f;
    for (int i = idx; i < 512; i += stride)      g_stats[i] = 0.f;
}

// ---------------- weight prep: fragment-order f16 weights ----------------
__global__ void k_prep(const float* __restrict__ Wo1, const float* __restrict__ Wo2,
                       const float* __restrict__ Win) {
    int i = blockIdx.x * blockDim.x + threadIdx.x;
    if (i < 16384) {
        int j = i & 1, nf = (i >> 1) & 3, lane = (i >> 3) & 31, wn = (i >> 8) & 3, c = i >> 10;
        int n = wn * 32 + nf * 8 + (lane >> 2);
        int k = c * 16 + (lane & 3) * 2 + j * 8;
        __half2 h = __floats2half2_rn(Wo1[k * 128 + n], Wo1[(k + 1) * 128 + n]);
        g_Wof1[i] = *(unsigned*)&h;
    }
    if (i < 8192) {
        int j = i & 1, nf = (i >> 1) & 3, lane = (i >> 3) & 31, wn = (i >> 8) & 3, c = i >> 10;
        int n = wn * 32 + nf * 8 + (lane >> 2);
        int k = c * 16 + (lane & 3) * 2 + j * 8;
        __half2 ha = __floats2half2_rn(Wo2[k * 128 + n], Wo2[(k + 1) * 128 + n]);
        g_Wof2[i] = *(unsigned*)&ha;
        __half2 hb = __floats2half2_rn(Win[k * 128 + n], Win[(k + 1) * 128 + n]);
        g_Wofin[i] = *(unsigned*)&hb;
    }
}

// ---------------- segment counts ----------------
__global__ void k_counts(const int* __restrict__ inv, const int* __restrict__ cin) {
    int i = blockIdx.x * blockDim.x + threadIdx.x;
    if (i < NV)   atomicAdd(&g_cntd[inv[i]], 1.0f);
    if (i < NPTS) atomicAdd(&g_cntv2[cin[i]], 1.0f);
}

// ---------------- identity = lrelu((f+v) @ W_in + b_in) -> f16 (tensor core, M-tile 64);
//                  fused scatter-add of x into g_ds. NV % 64 == 0. ----------------
__global__ void __launch_bounds__(256, 3) k_identity(
    const float* __restrict__ feat, const float* __restrict__ vfea,
    const int* __restrict__ inv, const float* __restrict__ bias) {
    __shared__ __half Asm[64][136];   // 17408 B

    const int tid  = threadIdx.x;
    const int lane = tid & 31;
    const int w    = tid >> 5;
    const int wm   = w & 1;
    const int wn   = w >> 1;
    const int g    = lane >> 2;
    const int tg   = lane & 3;
    const int m0   = blockIdx.x * 64;
    const int row  = tid >> 2;
    const int q    = tid & 3;          // cols [q*32, q*32+32)
    const int grow = m0 + row;
    const int seg  = inv[grow];

    const float* pf = feat + (size_t)grow * CD + q * 32;
    const float* pv = vfea + (size_t)grow * CD + q * 32;
    float*       pd = g_ds + (size_t)seg * CD + q * 32;

#pragma unroll
    for (int t = 0; t < 2; ++t) {
        __half2 h[8];
#pragma unroll
        for (int qq = 0; qq < 4; ++qq) {
            float4 f = *(const float4*)(pf + t * 16 + qq * 4);
            float4 v = *(const float4*)(pv + t * 16 + qq * 4);
            float4 x = make_float4(f.x + v.x, f.y + v.y, f.z + v.z, f.w + v.w);
            red_add_v4(pd + t * 16 + qq * 4, x);
            h[qq * 2]     = __floats2half2_rn(x.x, x.y);
            h[qq * 2 + 1] = __floats2half2_rn(x.z, x.w);
        }
        uint4 u0, u1;
        u0.x = *(unsigned*)&h[0]; u0.y = *(unsigned*)&h[1];
        u0.z = *(unsigned*)&h[2]; u0.w = *(unsigned*)&h[3];
        u1.x = *(unsigned*)&h[4]; u1.y = *(unsigned*)&h[5];
        u1.z = *(unsigned*)&h[6]; u1.w = *(unsigned*)&h[7];
        *(uint4*)&Asm[row][q * 32 + t * 16]     = u0;
        *(uint4*)&Asm[row][q * 32 + t * 16 + 8] = u1;
    }
    __syncthreads();

    float acc[2][4][4];
#pragma unroll
    for (int a = 0; a < 2; ++a)
#pragma unroll
        for (int b = 0; b < 4; ++b)
#pragma unroll
            for (int c = 0; c < 4; ++c) acc[a][b][c] = 0.f;

#pragma unroll
    for (int c = 0; c < 8; ++c) {
        unsigned af[2][4], bf[4][2];
#pragma unroll
        for (int mf = 0; mf < 2; ++mf) {
            int r0 = wm * 32 + mf * 16 + g;
            af[mf][0] = *(const unsigned*)&Asm[r0][c * 16 + tg * 2];
            af[mf][1] = *(const unsigned*)&Asm[r0 + 8][c * 16 + tg * 2];
            af[mf][2] = *(const unsigned*)&Asm[r0][c * 16 + tg * 2 + 8];
            af[mf][3] = *(const unsigned*)&Asm[r0 + 8][c * 16 + tg * 2 + 8];
        }
        const uint4* wf = (const uint4*)(g_Wofin + (((c * 4 + wn) * 32 + lane) << 3));
        uint4 u0 = wf[0], u1 = wf[1];
        bf[0][0] = u0.x; bf[0][1] = u0.y; bf[1][0] = u0.z; bf[1][1] = u0.w;
        bf[2][0] = u1.x; bf[2][1] = u1.y; bf[3][0] = u1.z; bf[3][1] = u1.w;
#pragma unroll
        for (int mf = 0; mf < 2; ++mf)
#pragma unroll
            for (int nf = 0; nf < 4; ++nf)
                mma16816(acc[mf][nf], af[mf], bf[nf]);
    }
    __syncthreads();

    // epilogue: bias+lrelu -> f16 staged in Asm -> coalesced store
#pragma unroll
    for (int mf = 0; mf < 2; ++mf) {
        int r0 = wm * 32 + mf * 16 + g;
#pragma unroll
        for (int nf = 0; nf < 4; ++nf) {
            int col = wn * 32 + nf * 8 + tg * 2;
            float b0 = bias[col], b1v = bias[col + 1];
            float* cc = acc[mf][nf];
            *(__half2*)&Asm[r0][col]     = __floats2half2_rn(lrelu(cc[0] + b0), lrelu(cc[1] + b1v));
            *(__half2*)&Asm[r0 + 8][col] = __floats2half2_rn(lrelu(cc[2] + b0), lrelu(cc[3] + b1v));
        }
    }
    __syncthreads();
#pragma unroll
    for (int t = 0; t < 4; ++t)
        *(uint4*)(g_idh + (size_t)grow * CD + q * 32 + t * 8) = *(const uint4*)&Asm[row][q * 32 + t * 8];
}

// ---------------- MLP stage 1: t1 = lrelu((ds/cnt) @ W1 + b1), stats ----------------
__global__ void __launch_bounds__(256) k_mlp1(const float* __restrict__ W, const float* __restrict__ bias) {
    __shared__ float As[2][8][128];
    __shared__ float Bs[2][8][64];
    __shared__ float ssum[64], ssq[64];
    const int tid = threadIdx.x;
    if (tid < 64) { ssum[tid] = 0.f; ssq[tid] = 0.f; }
    const int tx = tid & 7, ty = tid >> 3;
    const int m0 = blockIdx.x * 128;
    const int arow = tid >> 1, acol = (tid & 1) * 4;
    const int grow = m0 + arow;
    const bool rv = grow < ND;
    const float ic = rv ? 1.0f / fmaxf(g_cntd[grow], 1.0f) : 0.f;
    const int brow = tid >> 4, bcol = (tid & 15) * 4;

    float acc[4][8];
#pragma unroll
    for (int i = 0; i < 4; ++i)
#pragma unroll
        for (int j = 0; j < 8; ++j) acc[i][j] = 0.f;

    float4 aR = make_float4(0, 0, 0, 0), bR = make_float4(0, 0, 0, 0);
    if (rv) {
        float4 t = *(const float4*)(g_ds + (size_t)grow * CD + acol);
        aR = make_float4(t.x * ic, t.y * ic, t.z * ic, t.w * ic);
    }
    if (tid < 128) bR = *(const float4*)(W + brow * 64 + bcol);
    As[0][acol + 0][arow] = aR.x; As[0][acol + 1][arow] = aR.y;
    As[0][acol + 2][arow] = aR.z; As[0][acol + 3][arow] = aR.w;
    if (tid < 128) *(float4*)&Bs[0][brow][bcol] = bR;
    __syncthreads();

    for (int c = 0; c < 16; ++c) {
        const int cur = c & 1;
        if (c + 1 < 16) {
            if (rv) {
                float4 t = *(const float4*)(g_ds + (size_t)grow * CD + (c + 1) * 8 + acol);
                aR = make_float4(t.x * ic, t.y * ic, t.z * ic, t.w * ic);
            }
            if (tid < 128) bR = *(const float4*)(W + ((c + 1) * 8 + brow) * 64 + bcol);
        }
#pragma unroll
        for (int k = 0; k < 8; ++k) {
            float4 a = *(const float4*)&As[cur][k][ty * 4];
            float4 b0 = *(const float4*)&Bs[cur][k][tx * 8];
            float4 b1 = *(const float4*)&Bs[cur][k][tx * 8 + 4];
            float av[4] = {a.x, a.y, a.z, a.w};
            float bv[8] = {b0.x, b0.y, b0.z, b0.w, b1.x, b1.y, b1.z, b1.w};
#pragma unroll
            for (int i = 0; i < 4; ++i)
#pragma unroll
                for (int j = 0; j < 8; ++j)
                    acc[i][j] += av[i] * bv[j];
        }
        if (c + 1 < 16) {
            const int nb = cur ^ 1;
            As[nb][acol + 0][arow] = aR.x; As[nb][acol + 1][arow] = aR.y;
            As[nb][acol + 2][arow] = aR.z; As[nb][acol + 3][arow] = aR.w;
            if (tid < 128) *(float4*)&Bs[nb][brow][bcol] = bR;
        }
        __syncthreads();
    }

    float bb[8];
#pragma unroll
    for (int j = 0; j < 8; ++j) bb[j] = bias[tx * 8 + j];
    float cs[8], cq[8];
#pragma unroll
    for (int j = 0; j < 8; ++j) { cs[j] = 0.f; cq[j] = 0.f; }
#pragma unroll
    for (int i = 0; i < 4; ++i) {
        int r = m0 + ty * 4 + i;
        if (r < ND) {
            float o[8];
#pragma unroll
            for (int j = 0; j < 8; ++j) {
                o[j] = lrelu(acc[i][j] + bb[j]);
                cs[j] += o[j]; cq[j] += o[j] * o[j];
            }
            *(float4*)(g_t1 + (size_t)r * 64 + tx * 8)     = make_float4(o[0], o[1], o[2], o[3]);
            *(float4*)(g_t1 + (size_t)r * 64 + tx * 8 + 4) = make_float4(o[4], o[5], o[6], o[7]);
        }
    }
#pragma unroll
    for (int j = 0; j < 8; ++j) {
        atomicAdd(&ssum[tx * 8 + j], cs[j]);
        atomicAdd(&ssq[tx * 8 + j], cq[j]);
    }
    __syncthreads();
    if (tid < 64) {
        atomicAdd(&g_stats[tid], ssum[tid]);
        atomicAdd(&g_stats[128 + tid], ssq[tid]);
    }
}

// ---------------- MLP stage 2: t2 = lrelu(BN1(t1) @ W2 + b2), stats ----------------
__global__ void __launch_bounds__(256) k_mlp2(const float* __restrict__ gam, const float* __restrict__ bet,
                                              const float* __restrict__ W, const float* __restrict__ bias) {
    __shared__ float As[2][8][128];
    __shared__ float Bs[2][8][64];
    __shared__ float amul[64], aadd[64];
    __shared__ float ssum[64], ssq[64];
    const int tid = threadIdx.x;
    if (tid < 64) {
        const float im = 1.0f / (float)ND;
        float m = g_stats[tid] * im;
        float v = g_stats[128 + tid] * im - m * m;
        float gm = rsqrtf(v + 1e-5f) * gam[tid];
        amul[tid] = gm; aadd[tid] = bet[tid] - m * gm;
        ssum[tid] = 0.f; ssq[tid] = 0.f;
    }
    __syncthreads();
    const int tx = tid & 7, ty = tid >> 3;
    const int m0 = blockIdx.x * 128;
    const int arow = tid >> 1, acol = (tid & 1) * 4;
    const int grow = m0 + arow;
    const bool rv = grow < ND;
    const int brow = tid >> 4, bcol = (tid & 15) * 4;

    float acc[4][8];
#pragma unroll
    for (int i = 0; i < 4; ++i)
#pragma unroll
        for (int j = 0; j < 8; ++j) acc[i][j] = 0.f;

    float4 aR = make_float4(0, 0, 0, 0), bR = make_float4(0, 0, 0, 0);
    if (rv) {
        float4 t = *(const float4*)(g_t1 + (size_t)grow * 64 + acol);
        float4 mm = *(const float4*)&amul[acol];
        float4 ad = *(const float4*)&aadd[acol];
        aR = make_float4(t.x * mm.x + ad.x, t.y * mm.y + ad.y, t.z * mm.z + ad.z, t.w * mm.w + ad.w);
    }
    if (tid < 128) bR = *(const float4*)(W + brow * 64 + bcol);
    As[0][acol + 0][arow] = aR.x; As[0][acol + 1][arow] = aR.y;
    As[0][acol + 2][arow] = aR.z; As[0][acol + 3][arow] = aR.w;
    if (tid < 128) *(float4*)&Bs[0][brow][bcol] = bR;
    __syncthreads();

    for (int c = 0; c < 8; ++c) {
        const int cur = c & 1;
        if (c + 1 < 8) {
            if (rv) {
                int col = (c + 1) * 8 + acol;
                float4 t = *(const float4*)(g_t1 + (size_t)grow * 64 + col);
                float4 mm = *(const float4*)&amul[col];
                float4 ad = *(const float4*)&aadd[col];
                aR = make_float4(t.x * mm.x + ad.x, t.y * mm.y + ad.y, t.z * mm.z + ad.z, t.w * mm.w + ad.w);
            }
            if (tid < 128) bR = *(const float4*)(W + ((c + 1) * 8 + brow) * 64 + bcol);
        }
#pragma unroll
        for (int k = 0; k < 8; ++k) {
            float4 a = *(const float4*)&As[cur][k][ty * 4];
            float4 b0 = *(const float4*)&Bs[cur][k][tx * 8];
            float4 b1 = *(const float4*)&Bs[cur][k][tx * 8 + 4];
            float av[4] = {a.x, a.y, a.z, a.w};
            float bv[8] = {b0.x, b0.y, b0.z, b0.w, b1.x, b1.y, b1.z, b1.w};
#pragma unroll
            for (int i = 0; i < 4; ++i)
#pragma unroll
                for (int j = 0; j < 8; ++j)
                    acc[i][j] += av[i] * bv[j];
        }
        if (c + 1 < 8) {
            const int nb = cur ^ 1;
            As[nb][acol + 0][arow] = aR.x; As[nb][acol + 1][arow] = aR.y;
            As[nb][acol + 2][arow] = aR.z; As[nb][acol + 3][arow] = aR.w;
            if (tid < 128) *(float4*)&Bs[nb][brow][bcol] = bR;
        }
        __syncthreads();
    }

    float bb[8];
#pragma unroll
    for (int j = 0; j < 8; ++j) bb[j] = bias[tx * 8 + j];
    float cs[8], cq[8];
#pragma unroll
    for (int j = 0; j < 8; ++j) { cs[j] = 0.f; cq[j] = 0.f; }
#pragma unroll
    for (int i = 0; i < 4; ++i) {
        int r = m0 + ty * 4 + i;
        if (r < ND) {
            float o[8];
#pragma unroll
            for (int j = 0; j < 8; ++j) {
                o[j] = lrelu(acc[i][j] + bb[j]);
                cs[j] += o[j]; cq[j] += o[j] * o[j];
            }
            *(float4*)(g_t2 + (size_t)r * 64 + tx * 8)     = make_float4(o[0], o[1], o[2], o[3]);
            *(float4*)(g_t2 + (size_t)r * 64 + tx * 8 + 4) = make_float4(o[4], o[5], o[6], o[7]);
        }
    }
#pragma unroll
    for (int j = 0; j < 8; ++j) {
        atomicAdd(&ssum[tx * 8 + j], cs[j]);
        atomicAdd(&ssq[tx * 8 + j], cq[j]);
    }
    __syncthreads();
    if (tid < 64) {
        atomicAdd(&g_stats[256 + tid], ssum[tid]);
        atomicAdd(&g_stats[384 + tid], ssq[tid]);
    }
}

// ---------------- MLP stage 3: hm = lrelu(BN2(t2) @ W3 + b3) -> f16 ----------------
__global__ void __launch_bounds__(256) k_mlp3(const float* __restrict__ gam, const float* __restrict__ bet,
                                              const float* __restrict__ W, const float* __restrict__ bias) {
    __shared__ float As[2][8][128];
    __shared__ float Bs[2][8][128];
    __shared__ float amul[64], aadd[64];
    const int tid = threadIdx.x;
    if (tid < 64) {
        const float im = 1.0f / (float)ND;
        float m = g_stats[256 + tid] * im;
        float v = g_stats[384 + tid] * im - m * m;
        float gm = rsqrtf(v + 1e-5f) * gam[tid];
        amul[tid] = gm; aadd[tid] = bet[tid] - m * gm;
    }
    __syncthreads();
    const int tx = tid & 15, ty = tid >> 4;
    const int m0 = blockIdx.x * 128;
    const int arow = tid >> 1, acol = (tid & 1) * 4;
    const int grow = m0 + arow;
    const bool rv = grow < ND;
    const int brow = tid >> 5, bcol = (tid & 31) * 4;

    float acc[8][8];
#pragma unroll
    for (int i = 0; i < 8; ++i)
#pragma unroll
        for (int j = 0; j < 8; ++j) acc[i][j] = 0.f;

    float4 aR = make_float4(0, 0, 0, 0), bR;
    if (rv) {
        float4 t = *(const float4*)(g_t2 + (size_t)grow * 64 + acol);
        float4 mm = *(const float4*)&amul[acol];
        float4 ad = *(const float4*)&aadd[acol];
        aR = make_float4(t.x * mm.x + ad.x, t.y * mm.y + ad.y, t.z * mm.z + ad.z, t.w * mm.w + ad.w);
    }
    bR = *(const float4*)(W + brow * CD + bcol);
    As[0][acol + 0][arow] = aR.x; As[0][acol + 1][arow] = aR.y;
    As[0][acol + 2][arow] = aR.z; As[0][acol + 3][arow] = aR.w;
    *(float4*)&Bs[0][brow][bcol] = bR;
    __syncthreads();

    for (int c = 0; c < 8; ++c) {
        const int cur = c & 1;
        if (c + 1 < 8) {
            if (rv) {
                int col = (c + 1) * 8 + acol;
                float4 t = *(const float4*)(g_t2 + (size_t)grow * 64 + col);
                float4 mm = *(const float4*)&amul[col];
                float4 ad = *(const float4*)&aadd[col];
                aR = make_float4(t.x * mm.x + ad.x, t.y * mm.y + ad.y, t.z * mm.z + ad.z, t.w * mm.w + ad.w);
            } else aR = make_float4(0, 0, 0, 0);
            bR = *(const float4*)(W + ((c + 1) * 8 + brow) * CD + bcol);
        }
#pragma unroll
        for (int k = 0; k < 8; ++k) {
            float4 a0 = *(const float4*)&As[cur][k][ty * 8];
            float4 a1 = *(const float4*)&As[cur][k][ty * 8 + 4];
            float4 b0 = *(const float4*)&Bs[cur][k][tx * 8];
            float4 b1 = *(const float4*)&Bs[cur][k][tx * 8 + 4];
            float av[8] = {a0.x, a0.y, a0.z, a0.w, a1.x, a1.y, a1.z, a1.w};
            float bv[8] = {b0.x, b0.y, b0.z, b0.w, b1.x, b1.y, b1.z, b1.w};
#pragma unroll
            for (int i = 0; i < 8; ++i)
#pragma unroll
                for (int j = 0; j < 8; ++j)
                    acc[i][j] += av[i] * bv[j];
        }
        if (c + 1 < 8) {
            const int nb = cur ^ 1;
            As[nb][acol + 0][arow] = aR.x; As[nb][acol + 1][arow] = aR.y;
            As[nb][acol + 2][arow] = aR.z; As[nb][acol + 3][arow] = aR.w;
            *(float4*)&Bs[nb][brow][bcol] = bR;
        }
        __syncthreads();
    }

    float bb[8];
#pragma unroll
    for (int j = 0; j < 8; ++j) bb[j] = bias[tx * 8 + j];
#pragma unroll
    for (int i = 0; i < 8; ++i) {
        int r = m0 + ty * 8 + i;
        if (r < ND) {
            __half2 h[4];
#pragma unroll
            for (int j = 0; j < 4; ++j)
                h[j] = __floats2half2_rn(lrelu(acc[i][2 * j] + bb[2 * j]),
                                         lrelu(acc[i][2 * j + 1] + bb[2 * j + 1]));
            uint4 u;
            u.x = *(unsigned*)&h[0]; u.y = *(unsigned*)&h[1];
            u.z = *(unsigned*)&h[2]; u.w = *(unsigned*)&h[3];
            *(uint4*)(g_hmh + (size_t)r * CD + tx * 8) = u;
        }
    }
}

// ---------------- fused point path: direct-global A fragments, 2 syncs total ----------------
__global__ void __launch_bounds__(256, 2) k_points(
    const int* __restrict__ cil, const int* __restrict__ cin, const int* __restrict__ inv,
    const float* __restrict__ bo1, const float* __restrict__ bo2) {
    extern __shared__ __align__(16) char smp[];
    __half (*Hs)[136] = (__half (*)[136])smp;      // 34816 B
    int* sv = (int*)(smp + 34816);
    int* sw = sv + 128;
    int* ss = sw + 128;                            // total 36352 B

    const int tid  = threadIdx.x;
    const int lane = tid & 31;
    const int w    = tid >> 5;
    const int wm   = w & 1;
    const int wn   = w >> 1;
    const int g    = lane >> 2;
    const int tg   = lane & 3;
    const int m0   = blockIdx.x * 128;   // NPTS % 128 == 0

    if (tid < 128) {
        int p = m0 + tid;
        int v = cil[p];
        sv[tid] = v;
        sw[tid] = inv[v];
        ss[tid] = cin[p];
    }
    __syncthreads();

    int rid[8], rhm[8];
#pragma unroll
    for (int mf = 0; mf < 4; ++mf) {
        int r0 = wm * 64 + mf * 16 + g;
        rid[2 * mf] = sv[r0]; rid[2 * mf + 1] = sv[r0 + 8];
        rhm[2 * mf] = sw[r0]; rhm[2 * mf + 1] = sw[r0 + 8];
    }

    float acc[4][4][4];
#pragma unroll
    for (int a = 0; a < 4; ++a)
#pragma unroll
        for (int b = 0; b < 4; ++b)
#pragma unroll
            for (int c = 0; c < 4; ++c) acc[a][b][c] = 0.f;

    // ---- stage 1a: identity columns (frag chunks 0..7), no smem, no syncs ----
#pragma unroll
    for (int c = 0; c < 8; ++c) {
        int ko = c * 16 + tg * 2;
        unsigned af[4][4], bf[4][2];
#pragma unroll
        for (int mf = 0; mf < 4; ++mf) {
            const __half* p0 = g_idh + (size_t)rid[2 * mf] * CD + ko;
            const __half* p1 = g_idh + (size_t)rid[2 * mf + 1] * CD + ko;
            af[mf][0] = *(const unsigned*)p0;
            af[mf][1] = *(const unsigned*)p1;
            af[mf][2] = *(const unsigned*)(p0 + 8);
            af[mf][3] = *(const unsigned*)(p1 + 8);
        }
        const uint4* wf = (const uint4*)(g_Wof1 + (((c * 4 + wn) * 32 + lane) << 3));
        uint4 u0 = wf[0], u1 = wf[1];
        bf[0][0] = u0.x; bf[0][1] = u0.y; bf[1][0] = u0.z; bf[1][1] = u0.w;
        bf[2][0] = u1.x; bf[2][1] = u1.y; bf[3][0] = u1.z; bf[3][1] = u1.w;
#pragma unroll
        for (int mf = 0; mf < 4; ++mf)
#pragma unroll
            for (int nf = 0; nf < 4; ++nf)
                mma16816(acc[mf][nf], af[mf], bf[nf]);
    }
    // ---- stage 1b: hm columns (frag chunks 8..15) ----
#pragma unroll
    for (int c = 0; c < 8; ++c) {
        int ko = c * 16 + tg * 2;
        unsigned af[4][4], bf[4][2];
#pragma unroll
        for (int mf = 0; mf < 4; ++mf) {
            const __half* p0 = g_hmh + (size_t)rhm[2 * mf] * CD + ko;
            const __half* p1 = g_hmh + (size_t)rhm[2 * mf + 1] * CD + ko;
            af[mf][0] = *(const unsigned*)p0;
            af[mf][1] = *(const unsigned*)p1;
            af[mf][2] = *(const unsigned*)(p0 + 8);
            af[mf][3] = *(const unsigned*)(p1 + 8);
        }
        const uint4* wf = (const uint4*)(g_Wof1 + ((((c + 8) * 4 + wn) * 32 + lane) << 3));
        uint4 u0 = wf[0], u1 = wf[1];
        bf[0][0] = u0.x; bf[0][1] = u0.y; bf[1][0] = u0.z; bf[1][1] = u0.w;
        bf[2][0] = u1.x; bf[2][1] = u1.y; bf[3][0] = u1.z; bf[3][1] = u1.w;
#pragma unroll
        for (int mf = 0; mf < 4; ++mf)
#pragma unroll
            for (int nf = 0; nf < 4; ++nf)
                mma16816(acc[mf][nf], af[mf], bf[nf]);
    }

    // ---- epilogue 1: H -> SMEM f16, reset acc ----
#pragma unroll
    for (int mf = 0; mf < 4; ++mf) {
        int r0 = wm * 64 + mf * 16 + g;
#pragma unroll
        for (int nf = 0; nf < 4; ++nf) {
            int col = wn * 32 + nf * 8 + tg * 2;
            float b0 = bo1[col], b1v = bo1[col + 1];
            float* cc = acc[mf][nf];
            *(__half2*)&Hs[r0][col]     = __floats2half2_rn(lrelu(cc[0] + b0), lrelu(cc[1] + b1v));
            *(__half2*)&Hs[r0 + 8][col] = __floats2half2_rn(lrelu(cc[2] + b0), lrelu(cc[3] + b1v));
            cc[0] = cc[1] = cc[2] = cc[3] = 0.f;
        }
    }
    __syncthreads();

    // ---- stage 2: K=128, A from Hs (read-only), B from g_Wof2, no syncs ----
#pragma unroll
    for (int c = 0; c < 8; ++c) {
        unsigned af[4][4], bf[4][2];
#pragma unroll
        for (int mf = 0; mf < 4; ++mf) {
            int r0 = wm * 64 + mf * 16 + g;
            af[mf][0] = *(const unsigned*)&Hs[r0][c * 16 + tg * 2];
            af[mf][1] = *(const unsigned*)&Hs[r0 + 8][c * 16 + tg * 2];
            af[mf][2] = *(const unsigned*)&Hs[r0][c * 16 + tg * 2 + 8];
            af[mf][3] = *(const unsigned*)&Hs[r0 + 8][c * 16 + tg * 2 + 8];
        }
        const uint4* wf = (const uint4*)(g_Wof2 + (((c * 4 + wn) * 32 + lane) << 3));
        uint4 u0 = wf[0], u1 = wf[1];
        bf[0][0] = u0.x; bf[0][1] = u0.y; bf[1][0] = u0.z; bf[1][1] = u0.w;
        bf[2][0] = u1.x; bf[2][1] = u1.y; bf[3][0] = u1.z; bf[3][1] = u1.w;
#pragma unroll
        for (int mf = 0; mf < 4; ++mf)
#pragma unroll
            for (int nf = 0; nf < 4; ++nf)
                mma16816(acc[mf][nf], af[mf], bf[nf]);
    }

    // ---- epilogue 2: Y -> segment sums (v2 reductions) ----
#pragma unroll
    for (int mf = 0; mf < 4; ++mf) {
        int r0 = wm * 64 + mf * 16 + g;
        int s0 = ss[r0], s1 = ss[r0 + 8];
#pragma unroll
        for (int nf = 0; nf < 4; ++nf) {
            int col = wn * 32 + nf * 8 + tg * 2;
            float b0 = bo2[col], b1v = bo2[col + 1];
            float* cc = acc[mf][nf];
            red_add_v2(g_pfea + (size_t)s0 * CD + col, cc[0] + b0, cc[1] + b1v);
            red_add_v2(g_pfea + (size_t)s1 * CD + col, cc[2] + b0, cc[3] + b1v);
        }
    }
}

// ---------------- out[p] = pfea_sum[cin[p]] / max(cnt,1) ----------------
__global__ void k_gather(const int* __restrict__ cin, float* __restrict__ out) {
    int idx = blockIdx.x * blockDim.x + threadIdx.x;
    if (idx >= NPTS * 32) return;
    int p = idx >> 5;
    int c = (idx & 31) * 4;
    int s = cin[p];
    float ic = 1.0f / fmaxf(g_cntv2[s], 1.0f);
    float4 v = *(const float4*)(g_pfea + (size_t)s * CD + c);
    *(float4*)(out + (size_t)p * CD + c) = make_float4(v.x * ic, v.y * ic, v.z * ic, v.w * ic);
}

// ---------------- launch ----------------
extern "C" void kernel_launch(void* const* d_in, const int* in_sizes, int n_in,
                              void* d_out, int out_size) {
    const float* feat = (const float*)d_in[0];
    const float* vfea = (const float*)d_in[1];
    const int*   inv  = (const int*)d_in[2];
    const int*   cil  = (const int*)d_in[3];
    const int*   cin  = (const int*)d_in[4];
    const float* W_in = (const float*)d_in[5];
    const float* b_in = (const float*)d_in[6];
    const float* W1   = (const float*)d_in[7];
    const float* b1   = (const float*)d_in[8];
    const float* g1   = (const float*)d_in[9];
    const float* be1  = (const float*)d_in[10];
    const float* W2   = (const float*)d_in[11];
    const float* b2   = (const float*)d_in[12];
    const float* g2   = (const float*)d_in[13];
    const float* be2  = (const float*)d_in[14];
    const float* W3   = (const float*)d_in[15];
    const float* b3   = (const float*)d_in[16];
    const float* Wo1  = (const float*)d_in[17];
    const float* bo1  = (const float*)d_in[18];
    const float* Wo2  = (const float*)d_in[19];
    const float* bo2  = (const float*)d_in[20];
    float* out = (float*)d_out;

    const int PTS_SMEM = 36352;
    cudaFuncSetAttribute(k_points, cudaFuncAttributeMaxDynamicSharedMemorySize, PTS_SMEM);

    k_zero<<<2048, 256>>>();
    k_prep<<<64, 256>>>(Wo1, Wo2, W_in);
    k_counts<<<(NPTS + 255) / 256, 256>>>(inv, cin);
    k_identity<<<NV / 64, 256>>>(feat, vfea, inv, b_in);
    k_mlp1<<<(ND + 127) / 128, 256>>>(W1, b1);
    k_mlp2<<<(ND + 127) / 128, 256>>>(g1, be1, W2, b2);
    k_mlp3<<<(ND + 127) / 128, 256>>>(g2, be2, W3, b3);
    k_points<<<NPTS / 128, 256, PTS_SMEM>>>(cil, cin, inv, bo1, bo2);
    k_gather<<<(NPTS * 32) / 256, 256>>>(cin, out);
}

// round 5
// speedup vs baseline: 1.2070x; 1.2070x over previous
#include <cuda_runtime.h>
#include <cuda_fp16.h>

#define NV   120000
#define ND   30000
#define NV2  60000
#define NPTS 400000
#define CD   128
#define HD   64

// ---------------- scratch (static device globals; no allocation) ----------------
__device__ float  g_ds[ND * CD];          // segment sums of x
__device__ float  g_cntd[ND];
__device__ __half g_idh[NV * CD];         // identity, f16
__device__ float  g_t1[ND * HD];
__device__ float  g_t2[ND * HD];
__device__ __half g_hmh[ND * CD];         // hm, f16
__device__ float  g_pfea[NV2 * CD];       // segment sums of pts
__device__ float  g_cntv2[NV2];
__device__ float  g_stats[512];
// fragment-layout weights: idx = ((c*4 + wn)*32 + lane)*8 + nf*2 + j
__device__ __align__(16) unsigned g_Wof1[16 * 4 * 32 * 8];   // Wo1 (K=256): 64KB
__device__ __align__(16) unsigned g_Wof2[8 * 4 * 32 * 8];    // Wo2 (K=128): 32KB
__device__ __align__(16) unsigned g_Wofin[8 * 4 * 32 * 8];   // W_in (K=128): 32KB

__device__ __forceinline__ float lrelu(float x) { return x > 0.f ? x : 0.1f * x; }

__device__ __forceinline__ void red_add_v4(float* p, float4 v) {
    asm volatile("red.global.add.v4.f32 [%0], {%1,%2,%3,%4};"
                 :: "l"(p), "f"(v.x), "f"(v.y), "f"(v.z), "f"(v.w) : "memory");
}
__device__ __forceinline__ void red_add_v2(float* p, float a, float b) {
    asm volatile("red.global.add.v2.f32 [%0], {%1,%2};"
                 :: "l"(p), "f"(a), "f"(b) : "memory");
}
__device__ __forceinline__ void mma16816(float* c, const unsigned* a, const unsigned* b) {
    asm volatile("mma.sync.aligned.m16n8k16.row.col.f32.f16.f16.f32 "
                 "{%0,%1,%2,%3},{%4,%5,%6,%7},{%8,%9},{%0,%1,%2,%3};"
                 : "+f"(c[0]), "+f"(c[1]), "+f"(c[2]), "+f"(c[3])
                 : "r"(a[0]), "r"(a[1]), "r"(a[2]), "r"(a[3]), "r"(b[0]), "r"(b[1]));
}

// ---------------- zero scratch ----------------
__global__ void k_zero() {
    int idx = blockIdx.x * blockDim.x + threadIdx.x;
    int stride = gridDim.x * blockDim.x;
    for (int i = idx; i < ND * CD; i += stride)  g_ds[i] = 0.f;
    for (int i = idx; i < ND; i += stride)       g_cntd[i] = 0.f;
    for (int i = idx; i < NV2 * CD; i += stride) g_pfea[i] = 0.f;
    for (int i = idx; i < NV2; i += stride)      g_cntv2[i] = 0.f;
    for (int i = idx; i < 512; i += stride)      g_stats[i] = 0.f;
}

// ---------------- weight prep: fragment-order f16 weights ----------------
__global__ void k_prep(const float* __restrict__ Wo1, const float* __restrict__ Wo2,
                       const float* __restrict__ Win) {
    int i = blockIdx.x * blockDim.x + threadIdx.x;
    if (i < 16384) {
        int j = i & 1, nf = (i >> 1) & 3, lane = (i >> 3) & 31, wn = (i >> 8) & 3, c = i >> 10;
        int n = wn * 32 + nf * 8 + (lane >> 2);
        int k = c * 16 + (lane & 3) * 2 + j * 8;
        __half2 h = __floats2half2_rn(Wo1[k * 128 + n], Wo1[(k + 1) * 128 + n]);
        g_Wof1[i] = *(unsigned*)&h;
    }
    if (i < 8192) {
        int j = i & 1, nf = (i >> 1) & 3, lane = (i >> 3) & 31, wn = (i >> 8) & 3, c = i >> 10;
        int n = wn * 32 + nf * 8 + (lane >> 2);
        int k = c * 16 + (lane & 3) * 2 + j * 8;
        __half2 ha = __floats2half2_rn(Wo2[k * 128 + n], Wo2[(k + 1) * 128 + n]);
        g_Wof2[i] = *(unsigned*)&ha;
        __half2 hb = __floats2half2_rn(Win[k * 128 + n], Win[(k + 1) * 128 + n]);
        g_Wofin[i] = *(unsigned*)&hb;
    }
}

// ---------------- segment counts ----------------
__global__ void k_counts(const int* __restrict__ inv, const int* __restrict__ cin) {
    int i = blockIdx.x * blockDim.x + threadIdx.x;
    if (i < NV)   atomicAdd(&g_cntd[inv[i]], 1.0f);
    if (i < NPTS) atomicAdd(&g_cntv2[cin[i]], 1.0f);
}

// ---------------- identity = lrelu((f+v) @ W_in + b_in) -> f16 (tensor core, M-tile 64);
//                  fused scatter-add of x into g_ds. NV % 64 == 0. ----------------
__global__ void __launch_bounds__(256, 3) k_identity(
    const float* __restrict__ feat, const float* __restrict__ vfea,
    const int* __restrict__ inv, const float* __restrict__ bias) {
    __shared__ __half Asm[64][136];   // 17408 B

    const int tid  = threadIdx.x;
    const int lane = tid & 31;
    const int w    = tid >> 5;
    const int wm   = w & 1;
    const int wn   = w >> 1;
    const int g    = lane >> 2;
    const int tg   = lane & 3;
    const int m0   = blockIdx.x * 64;
    const int row  = tid >> 2;
    const int q    = tid & 3;          // cols [q*32, q*32+32)
    const int grow = m0 + row;
    const int seg  = inv[grow];

    const float* pf = feat + (size_t)grow * CD + q * 32;
    const float* pv = vfea + (size_t)grow * CD + q * 32;
    float*       pd = g_ds + (size_t)seg * CD + q * 32;

#pragma unroll
    for (int t = 0; t < 2; ++t) {
        __half2 h[8];
#pragma unroll
        for (int qq = 0; qq < 4; ++qq) {
            float4 f = *(const float4*)(pf + t * 16 + qq * 4);
            float4 v = *(const float4*)(pv + t * 16 + qq * 4);
            float4 x = make_float4(f.x + v.x, f.y + v.y, f.z + v.z, f.w + v.w);
            red_add_v4(pd + t * 16 + qq * 4, x);
            h[qq * 2]     = __floats2half2_rn(x.x, x.y);
            h[qq * 2 + 1] = __floats2half2_rn(x.z, x.w);
        }
        uint4 u0, u1;
        u0.x = *(unsigned*)&h[0]; u0.y = *(unsigned*)&h[1];
        u0.z = *(unsigned*)&h[2]; u0.w = *(unsigned*)&h[3];
        u1.x = *(unsigned*)&h[4]; u1.y = *(unsigned*)&h[5];
        u1.z = *(unsigned*)&h[6]; u1.w = *(unsigned*)&h[7];
        *(uint4*)&Asm[row][q * 32 + t * 16]     = u0;
        *(uint4*)&Asm[row][q * 32 + t * 16 + 8] = u1;
    }
    __syncthreads();

    float acc[2][4][4];
#pragma unroll
    for (int a = 0; a < 2; ++a)
#pragma unroll
        for (int b = 0; b < 4; ++b)
#pragma unroll
            for (int c = 0; c < 4; ++c) acc[a][b][c] = 0.f;

#pragma unroll
    for (int c = 0; c < 8; ++c) {
        unsigned af[2][4], bf[4][2];
#pragma unroll
        for (int mf = 0; mf < 2; ++mf) {
            int r0 = wm * 32 + mf * 16 + g;
            af[mf][0] = *(const unsigned*)&Asm[r0][c * 16 + tg * 2];
            af[mf][1] = *(const unsigned*)&Asm[r0 + 8][c * 16 + tg * 2];
            af[mf][2] = *(const unsigned*)&Asm[r0][c * 16 + tg * 2 + 8];
            af[mf][3] = *(const unsigned*)&Asm[r0 + 8][c * 16 + tg * 2 + 8];
        }
        const uint4* wf = (const uint4*)(g_Wofin + (((c * 4 + wn) * 32 + lane) << 3));
        uint4 u0 = wf[0], u1 = wf[1];
        bf[0][0] = u0.x; bf[0][1] = u0.y; bf[1][0] = u0.z; bf[1][1] = u0.w;
        bf[2][0] = u1.x; bf[2][1] = u1.y; bf[3][0] = u1.z; bf[3][1] = u1.w;
#pragma unroll
        for (int mf = 0; mf < 2; ++mf)
#pragma unroll
            for (int nf = 0; nf < 4; ++nf)
                mma16816(acc[mf][nf], af[mf], bf[nf]);
    }
    __syncthreads();

    // epilogue: bias+lrelu -> f16 staged in Asm -> coalesced store
#pragma unroll
    for (int mf = 0; mf < 2; ++mf) {
        int r0 = wm * 32 + mf * 16 + g;
#pragma unroll
        for (int nf = 0; nf < 4; ++nf) {
            int col = wn * 32 + nf * 8 + tg * 2;
            float b0 = bias[col], b1v = bias[col + 1];
            float* cc = acc[mf][nf];
            *(__half2*)&Asm[r0][col]     = __floats2half2_rn(lrelu(cc[0] + b0), lrelu(cc[1] + b1v));
            *(__half2*)&Asm[r0 + 8][col] = __floats2half2_rn(lrelu(cc[2] + b0), lrelu(cc[3] + b1v));
        }
    }
    __syncthreads();
#pragma unroll
    for (int t = 0; t < 4; ++t)
        *(uint4*)(g_idh + (size_t)grow * CD + q * 32 + t * 8) = *(const uint4*)&Asm[row][q * 32 + t * 8];
}

// ---------------- MLP stage 1: t1 = lrelu((ds/cnt) @ W1 + b1), stats ----------------
__global__ void __launch_bounds__(256) k_mlp1(const float* __restrict__ W, const float* __restrict__ bias) {
    __shared__ float As[2][8][128];
    __shared__ float Bs[2][8][64];
    __shared__ float ssum[64], ssq[64];
    const int tid = threadIdx.x;
    if (tid < 64) { ssum[tid] = 0.f; ssq[tid] = 0.f; }
    const int tx = tid & 7, ty = tid >> 3;
    const int m0 = blockIdx.x * 128;
    const int arow = tid >> 1, acol = (tid & 1) * 4;
    const int grow = m0 + arow;
    const bool rv = grow < ND;
    const float ic = rv ? 1.0f / fmaxf(g_cntd[grow], 1.0f) : 0.f;
    const int brow = tid >> 4, bcol = (tid & 15) * 4;

    float acc[4][8];
#pragma unroll
    for (int i = 0; i < 4; ++i)
#pragma unroll
        for (int j = 0; j < 8; ++j) acc[i][j] = 0.f;

    float4 aR = make_float4(0, 0, 0, 0), bR = make_float4(0, 0, 0, 0);
    if (rv) {
        float4 t = *(const float4*)(g_ds + (size_t)grow * CD + acol);
        aR = make_float4(t.x * ic, t.y * ic, t.z * ic, t.w * ic);
    }
    if (tid < 128) bR = *(const float4*)(W + brow * 64 + bcol);
    As[0][acol + 0][arow] = aR.x; As[0][acol + 1][arow] = aR.y;
    As[0][acol + 2][arow] = aR.z; As[0][acol + 3][arow] = aR.w;
    if (tid < 128) *(float4*)&Bs[0][brow][bcol] = bR;
    __syncthreads();

    for (int c = 0; c < 16; ++c) {
        const int cur = c & 1;
        if (c + 1 < 16) {
            if (rv) {
                float4 t = *(const float4*)(g_ds + (size_t)grow * CD + (c + 1) * 8 + acol);
                aR = make_float4(t.x * ic, t.y * ic, t.z * ic, t.w * ic);
            }
            if (tid < 128) bR = *(const float4*)(W + ((c + 1) * 8 + brow) * 64 + bcol);
        }
#pragma unroll
        for (int k = 0; k < 8; ++k) {
            float4 a = *(const float4*)&As[cur][k][ty * 4];
            float4 b0 = *(const float4*)&Bs[cur][k][tx * 8];
            float4 b1 = *(const float4*)&Bs[cur][k][tx * 8 + 4];
            float av[4] = {a.x, a.y, a.z, a.w};
            float bv[8] = {b0.x, b0.y, b0.z, b0.w, b1.x, b1.y, b1.z, b1.w};
#pragma unroll
            for (int i = 0; i < 4; ++i)
#pragma unroll
                for (int j = 0; j < 8; ++j)
                    acc[i][j] += av[i] * bv[j];
        }
        if (c + 1 < 16) {
            const int nb = cur ^ 1;
            As[nb][acol + 0][arow] = aR.x; As[nb][acol + 1][arow] = aR.y;
            As[nb][acol + 2][arow] = aR.z; As[nb][acol + 3][arow] = aR.w;
            if (tid < 128) *(float4*)&Bs[nb][brow][bcol] = bR;
        }
        __syncthreads();
    }

    float bb[8];
#pragma unroll
    for (int j = 0; j < 8; ++j) bb[j] = bias[tx * 8 + j];
    float cs[8], cq[8];
#pragma unroll
    for (int j = 0; j < 8; ++j) { cs[j] = 0.f; cq[j] = 0.f; }
#pragma unroll
    for (int i = 0; i < 4; ++i) {
        int r = m0 + ty * 4 + i;
        if (r < ND) {
            float o[8];
#pragma unroll
            for (int j = 0; j < 8; ++j) {
                o[j] = lrelu(acc[i][j] + bb[j]);
                cs[j] += o[j]; cq[j] += o[j] * o[j];
            }
            *(float4*)(g_t1 + (size_t)r * 64 + tx * 8)     = make_float4(o[0], o[1], o[2], o[3]);
            *(float4*)(g_t1 + (size_t)r * 64 + tx * 8 + 4) = make_float4(o[4], o[5], o[6], o[7]);
        }
    }
#pragma unroll
    for (int j = 0; j < 8; ++j) {
        atomicAdd(&ssum[tx * 8 + j], cs[j]);
        atomicAdd(&ssq[tx * 8 + j], cq[j]);
    }
    __syncthreads();
    if (tid < 64) {
        atomicAdd(&g_stats[tid], ssum[tid]);
        atomicAdd(&g_stats[128 + tid], ssq[tid]);
    }
}

// ---------------- MLP stage 2: t2 = lrelu(BN1(t1) @ W2 + b2), stats ----------------
__global__ void __launch_bounds__(256) k_mlp2(const float* __restrict__ gam, const float* __restrict__ bet,
                                              const float* __restrict__ W, const float* __restrict__ bias) {
    __shared__ float As[2][8][128];
    __shared__ float Bs[2][8][64];
    __shared__ float amul[64], aadd[64];
    __shared__ float ssum[64], ssq[64];
    const int tid = threadIdx.x;
    if (tid < 64) {
        const float im = 1.0f / (float)ND;
        float m = g_stats[tid] * im;
        float v = g_stats[128 + tid] * im - m * m;
        float gm = rsqrtf(v + 1e-5f) * gam[tid];
        amul[tid] = gm; aadd[tid] = bet[tid] - m * gm;
        ssum[tid] = 0.f; ssq[tid] = 0.f;
    }
    __syncthreads();
    const int tx = tid & 7, ty = tid >> 3;
    const int m0 = blockIdx.x * 128;
    const int arow = tid >> 1, acol = (tid & 1) * 4;
    const int grow = m0 + arow;
    const bool rv = grow < ND;
    const int brow = tid >> 4, bcol = (tid & 15) * 4;

    float acc[4][8];
#pragma unroll
    for (int i = 0; i < 4; ++i)
#pragma unroll
        for (int j = 0; j < 8; ++j) acc[i][j] = 0.f;

    float4 aR = make_float4(0, 0, 0, 0), bR = make_float4(0, 0, 0, 0);
    if (rv) {
        float4 t = *(const float4*)(g_t1 + (size_t)grow * 64 + acol);
        float4 mm = *(const float4*)&amul[acol];
        float4 ad = *(const float4*)&aadd[acol];
        aR = make_float4(t.x * mm.x + ad.x, t.y * mm.y + ad.y, t.z * mm.z + ad.z, t.w * mm.w + ad.w);
    }
    if (tid < 128) bR = *(const float4*)(W + brow * 64 + bcol);
    As[0][acol + 0][arow] = aR.x; As[0][acol + 1][arow] = aR.y;
    As[0][acol + 2][arow] = aR.z; As[0][acol + 3][arow] = aR.w;
    if (tid < 128) *(float4*)&Bs[0][brow][bcol] = bR;
    __syncthreads();

    for (int c = 0; c < 8; ++c) {
        const int cur = c & 1;
        if (c + 1 < 8) {
            if (rv) {
                int col = (c + 1) * 8 + acol;
                float4 t = *(const float4*)(g_t1 + (size_t)grow * 64 + col);
                float4 mm = *(const float4*)&amul[col];
                float4 ad = *(const float4*)&aadd[col];
                aR = make_float4(t.x * mm.x + ad.x, t.y * mm.y + ad.y, t.z * mm.z + ad.z, t.w * mm.w + ad.w);
            }
            if (tid < 128) bR = *(const float4*)(W + ((c + 1) * 8 + brow) * 64 + bcol);
        }
#pragma unroll
        for (int k = 0; k < 8; ++k) {
            float4 a = *(const float4*)&As[cur][k][ty * 4];
            float4 b0 = *(const float4*)&Bs[cur][k][tx * 8];
            float4 b1 = *(const float4*)&Bs[cur][k][tx * 8 + 4];
            float av[4] = {a.x, a.y, a.z, a.w};
            float bv[8] = {b0.x, b0.y, b0.z, b0.w, b1.x, b1.y, b1.z, b1.w};
#pragma unroll
            for (int i = 0; i < 4; ++i)
#pragma unroll
                for (int j = 0; j < 8; ++j)
                    acc[i][j] += av[i] * bv[j];
        }
        if (c + 1 < 8) {
            const int nb = cur ^ 1;
            As[nb][acol + 0][arow] = aR.x; As[nb][acol + 1][arow] = aR.y;
            As[nb][acol + 2][arow] = aR.z; As[nb][acol + 3][arow] = aR.w;
            if (tid < 128) *(float4*)&Bs[nb][brow][bcol] = bR;
        }
        __syncthreads();
    }

    float bb[8];
#pragma unroll
    for (int j = 0; j < 8; ++j) bb[j] = bias[tx * 8 + j];
    float cs[8], cq[8];
#pragma unroll
    for (int j = 0; j < 8; ++j) { cs[j] = 0.f; cq[j] = 0.f; }
#pragma unroll
    for (int i = 0; i < 4; ++i) {
        int r = m0 + ty * 4 + i;
        if (r < ND) {
            float o[8];
#pragma unroll
            for (int j = 0; j < 8; ++j) {
                o[j] = lrelu(acc[i][j] + bb[j]);
                cs[j] += o[j]; cq[j] += o[j] * o[j];
            }
            *(float4*)(g_t2 + (size_t)r * 64 + tx * 8)     = make_float4(o[0], o[1], o[2], o[3]);
            *(float4*)(g_t2 + (size_t)r * 64 + tx * 8 + 4) = make_float4(o[4], o[5], o[6], o[7]);
        }
    }
#pragma unroll
    for (int j = 0; j < 8; ++j) {
        atomicAdd(&ssum[tx * 8 + j], cs[j]);
        atomicAdd(&ssq[tx * 8 + j], cq[j]);
    }
    __syncthreads();
    if (tid < 64) {
        atomicAdd(&g_stats[256 + tid], ssum[tid]);
        atomicAdd(&g_stats[384 + tid], ssq[tid]);
    }
}

// ---------------- MLP stage 3: hm = lrelu(BN2(t2) @ W3 + b3) -> f16 ----------------
__global__ void __launch_bounds__(256) k_mlp3(const float* __restrict__ gam, const float* __restrict__ bet,
                                              const float* __restrict__ W, const float* __restrict__ bias) {
    __shared__ float As[2][8][128];
    __shared__ float Bs[2][8][128];
    __shared__ float amul[64], aadd[64];
    const int tid = threadIdx.x;
    if (tid < 64) {
        const float im = 1.0f / (float)ND;
        float m = g_stats[256 + tid] * im;
        float v = g_stats[384 + tid] * im - m * m;
        float gm = rsqrtf(v + 1e-5f) * gam[tid];
        amul[tid] = gm; aadd[tid] = bet[tid] - m * gm;
    }
    __syncthreads();
    const int tx = tid & 15, ty = tid >> 4;
    const int m0 = blockIdx.x * 128;
    const int arow = tid >> 1, acol = (tid & 1) * 4;
    const int grow = m0 + arow;
    const bool rv = grow < ND;
    const int brow = tid >> 5, bcol = (tid & 31) * 4;

    float acc[8][8];
#pragma unroll
    for (int i = 0; i < 8; ++i)
#pragma unroll
        for (int j = 0; j < 8; ++j) acc[i][j] = 0.f;

    float4 aR = make_float4(0, 0, 0, 0), bR;
    if (rv) {
        float4 t = *(const float4*)(g_t2 + (size_t)grow * 64 + acol);
        float4 mm = *(const float4*)&amul[acol];
        float4 ad = *(const float4*)&aadd[acol];
        aR = make_float4(t.x * mm.x + ad.x, t.y * mm.y + ad.y, t.z * mm.z + ad.z, t.w * mm.w + ad.w);
    }
    bR = *(const float4*)(W + brow * CD + bcol);
    As[0][acol + 0][arow] = aR.x; As[0][acol + 1][arow] = aR.y;
    As[0][acol + 2][arow] = aR.z; As[0][acol + 3][arow] = aR.w;
    *(float4*)&Bs[0][brow][bcol] = bR;
    __syncthreads();

    for (int c = 0; c < 8; ++c) {
        const int cur = c & 1;
        if (c + 1 < 8) {
            if (rv) {
                int col = (c + 1) * 8 + acol;
                float4 t = *(const float4*)(g_t2 + (size_t)grow * 64 + col);
                float4 mm = *(const float4*)&amul[col];
                float4 ad = *(const float4*)&aadd[col];
                aR = make_float4(t.x * mm.x + ad.x, t.y * mm.y + ad.y, t.z * mm.z + ad.z, t.w * mm.w + ad.w);
            } else aR = make_float4(0, 0, 0, 0);
            bR = *(const float4*)(W + ((c + 1) * 8 + brow) * CD + bcol);
        }
#pragma unroll
        for (int k = 0; k < 8; ++k) {
            float4 a0 = *(const float4*)&As[cur][k][ty * 8];
            float4 a1 = *(const float4*)&As[cur][k][ty * 8 + 4];
            float4 b0 = *(const float4*)&Bs[cur][k][tx * 8];
            float4 b1 = *(const float4*)&Bs[cur][k][tx * 8 + 4];
            float av[8] = {a0.x, a0.y, a0.z, a0.w, a1.x, a1.y, a1.z, a1.w};
            float bv[8] = {b0.x, b0.y, b0.z, b0.w, b1.x, b1.y, b1.z, b1.w};
#pragma unroll
            for (int i = 0; i < 8; ++i)
#pragma unroll
                for (int j = 0; j < 8; ++j)
                    acc[i][j] += av[i] * bv[j];
        }
        if (c + 1 < 8) {
            const int nb = cur ^ 1;
            As[nb][acol + 0][arow] = aR.x; As[nb][acol + 1][arow] = aR.y;
            As[nb][acol + 2][arow] = aR.z; As[nb][acol + 3][arow] = aR.w;
            *(float4*)&Bs[nb][brow][bcol] = bR;
        }
        __syncthreads();
    }

    float bb[8];
#pragma unroll
    for (int j = 0; j < 8; ++j) bb[j] = bias[tx * 8 + j];
#pragma unroll
    for (int i = 0; i < 8; ++i) {
        int r = m0 + ty * 8 + i;
        if (r < ND) {
            __half2 h[4];
#pragma unroll
            for (int j = 0; j < 4; ++j)
                h[j] = __floats2half2_rn(lrelu(acc[i][2 * j] + bb[2 * j]),
                                         lrelu(acc[i][2 * j + 1] + bb[2 * j + 1]));
            uint4 u;
            u.x = *(unsigned*)&h[0]; u.y = *(unsigned*)&h[1];
            u.z = *(unsigned*)&h[2]; u.w = *(unsigned*)&h[3];
            *(uint4*)(g_hmh + (size_t)r * CD + tx * 8) = u;
        }
    }
}

// ---------------- fused point path: SMEM-staged A (coalesced gathers) + fragment weights,
//                  one A buffer reused for id tile / hm tile / H. 6 syncs total. ----------------
__global__ void __launch_bounds__(256, 2) k_points(
    const int* __restrict__ cil, const int* __restrict__ cin, const int* __restrict__ inv,
    const float* __restrict__ bo1, const float* __restrict__ bo2) {
    extern __shared__ __align__(16) char smp[];
    __half (*At)[136] = (__half (*)[136])smp;      // 34816 B (A tile, then H)
    int* sv = (int*)(smp + 34816);
    int* sw = sv + 128;
    int* ss = sw + 128;                            // total 36352 B

    const int tid  = threadIdx.x;
    const int lane = tid & 31;
    const int w    = tid >> 5;
    const int wm   = w & 1;
    const int wn   = w >> 1;
    const int g    = lane >> 2;
    const int tg   = lane & 3;
    const int m0   = blockIdx.x * 128;   // NPTS % 128 == 0
    const int row  = tid >> 1;
    const int half = tid & 1;            // cols [half*64, half*64+64)

    if (tid < 128) {
        int p = m0 + tid;
        int v = cil[p];
        sv[tid] = v;
        sw[tid] = inv[v];
        ss[tid] = cin[p];
    }
    __syncthreads();

    float acc[4][4][4];
#pragma unroll
    for (int a = 0; a < 4; ++a)
#pragma unroll
        for (int b = 0; b < 4; ++b)
#pragma unroll
            for (int c = 0; c < 4; ++c) acc[a][b][c] = 0.f;

    // ---- gather identity tile (coalesced 16B) ----
    {
        const __half* src = g_idh + (size_t)sv[row] * CD + half * 64;
#pragma unroll
        for (int t = 0; t < 8; ++t)
            *(uint4*)&At[row][half * 64 + t * 8] = *(const uint4*)(src + t * 8);
    }
    __syncthreads();

    // ---- stage 1a: chunks 0..7 over identity columns ----
#pragma unroll
    for (int c = 0; c < 8; ++c) {
        unsigned af[4][4], bf[4][2];
#pragma unroll
        for (int mf = 0; mf < 4; ++mf) {
            int r0 = wm * 64 + mf * 16 + g;
            af[mf][0] = *(const unsigned*)&At[r0][c * 16 + tg * 2];
            af[mf][1] = *(const unsigned*)&At[r0 + 8][c * 16 + tg * 2];
            af[mf][2] = *(const unsigned*)&At[r0][c * 16 + tg * 2 + 8];
            af[mf][3] = *(const unsigned*)&At[r0 + 8][c * 16 + tg * 2 + 8];
        }
        const uint4* wf = (const uint4*)(g_Wof1 + (((c * 4 + wn) * 32 + lane) << 3));
        uint4 u0 = wf[0], u1 = wf[1];
        bf[0][0] = u0.x; bf[0][1] = u0.y; bf[1][0] = u0.z; bf[1][1] = u0.w;
        bf[2][0] = u1.x; bf[2][1] = u1.y; bf[3][0] = u1.z; bf[3][1] = u1.w;
#pragma unroll
        for (int mf = 0; mf < 4; ++mf)
#pragma unroll
            for (int nf = 0; nf < 4; ++nf)
                mma16816(acc[mf][nf], af[mf], bf[nf]);
    }
    __syncthreads();

    // ---- gather hm tile into the same buffer ----
    {
        const __half* src = g_hmh + (size_t)sw[row] * CD + half * 64;
#pragma unroll
        for (int t = 0; t < 8; ++t)
            *(uint4*)&At[row][half * 64 + t * 8] = *(const uint4*)(src + t * 8);
    }
    __syncthreads();

    // ---- stage 1b: chunks 8..15 over hm columns ----
#pragma unroll
    for (int c = 0; c < 8; ++c) {
        unsigned af[4][4], bf[4][2];
#pragma unroll
        for (int mf = 0; mf < 4; ++mf) {
            int r0 = wm * 64 + mf * 16 + g;
            af[mf][0] = *(const unsigned*)&At[r0][c * 16 + tg * 2];
            af[mf][1] = *(const unsigned*)&At[r0 + 8][c * 16 + tg * 2];
            af[mf][2] = *(const unsigned*)&At[r0][c * 16 + tg * 2 + 8];
            af[mf][3] = *(const unsigned*)&At[r0 + 8][c * 16 + tg * 2 + 8];
        }
        const uint4* wf = (const uint4*)(g_Wof1 + ((((c + 8) * 4 + wn) * 32 + lane) << 3));
        uint4 u0 = wf[0], u1 = wf[1];
        bf[0][0] = u0.x; bf[0][1] = u0.y; bf[1][0] = u0.z; bf[1][1] = u0.w;
        bf[2][0] = u1.x; bf[2][1] = u1.y; bf[3][0] = u1.z; bf[3][1] = u1.w;
#pragma unroll
        for (int mf = 0; mf < 4; ++mf)
#pragma unroll
            for (int nf = 0; nf < 4; ++nf)
                mma16816(acc[mf][nf], af[mf], bf[nf]);
    }
    __syncthreads();

    // ---- epilogue 1: H -> At, reset acc ----
#pragma unroll
    for (int mf = 0; mf < 4; ++mf) {
        int r0 = wm * 64 + mf * 16 + g;
#pragma unroll
        for (int nf = 0; nf < 4; ++nf) {
            int col = wn * 32 + nf * 8 + tg * 2;
            float b0 = bo1[col], b1v = bo1[col + 1];
            float* cc = acc[mf][nf];
            *(__half2*)&At[r0][col]     = __floats2half2_rn(lrelu(cc[0] + b0), lrelu(cc[1] + b1v));
            *(__half2*)&At[r0 + 8][col] = __floats2half2_rn(lrelu(cc[2] + b0), lrelu(cc[3] + b1v));
            cc[0] = cc[1] = cc[2] = cc[3] = 0.f;
        }
    }
    __syncthreads();

    // ---- stage 2: K=128, A from At (read-only), B from g_Wof2, no syncs ----
#pragma unroll
    for (int c = 0; c < 8; ++c) {
        unsigned af[4][4], bf[4][2];
#pragma unroll
        for (int mf = 0; mf < 4; ++mf) {
            int r0 = wm * 64 + mf * 16 + g;
            af[mf][0] = *(const unsigned*)&At[r0][c * 16 + tg * 2];
            af[mf][1] = *(const unsigned*)&At[r0 + 8][c * 16 + tg * 2];
            af[mf][2] = *(const unsigned*)&At[r0][c * 16 + tg * 2 + 8];
            af[mf][3] = *(const unsigned*)&At[r0 + 8][c * 16 + tg * 2 + 8];
        }
        const uint4* wf = (const uint4*)(g_Wof2 + (((c * 4 + wn) * 32 + lane) << 3));
        uint4 u0 = wf[0], u1 = wf[1];
        bf[0][0] = u0.x; bf[0][1] = u0.y; bf[1][0] = u0.z; bf[1][1] = u0.w;
        bf[2][0] = u1.x; bf[2][1] = u1.y; bf[3][0] = u1.z; bf[3][1] = u1.w;
#pragma unroll
        for (int mf = 0; mf < 4; ++mf)
#pragma unroll
            for (int nf = 0; nf < 4; ++nf)
                mma16816(acc[mf][nf], af[mf], bf[nf]);
    }

    // ---- epilogue 2: Y -> segment sums (v2 reductions) ----
#pragma unroll
    for (int mf = 0; mf < 4; ++mf) {
        int r0 = wm * 64 + mf * 16 + g;
        int s0 = ss[r0], s1 = ss[r0 + 8];
#pragma unroll
        for (int nf = 0; nf < 4; ++nf) {
            int col = wn * 32 + nf * 8 + tg * 2;
            float b0 = bo2[col], b1v = bo2[col + 1];
            float* cc = acc[mf][nf];
            red_add_v2(g_pfea + (size_t)s0 * CD + col, cc[0] + b0, cc[1] + b1v);
            red_add_v2(g_pfea + (size_t)s1 * CD + col, cc[2] + b0, cc[3] + b1v);
        }
    }
}

// ---------------- out[p] = pfea_sum[cin[p]] / max(cnt,1) ----------------
__global__ void k_gather(const int* __restrict__ cin, float* __restrict__ out) {
    int idx = blockIdx.x * blockDim.x + threadIdx.x;
    if (idx >= NPTS * 32) return;
    int p = idx >> 5;
    int c = (idx & 31) * 4;
    int s = cin[p];
    float ic = 1.0f / fmaxf(g_cntv2[s], 1.0f);
    float4 v = *(const float4*)(g_pfea + (size_t)s * CD + c);
    *(float4*)(out + (size_t)p * CD + c) = make_float4(v.x * ic, v.y * ic, v.z * ic, v.w * ic);
}

// ---------------- launch ----------------
extern "C" void kernel_launch(void* const* d_in, const int* in_sizes, int n_in,
                              void* d_out, int out_size) {
    const float* feat = (const float*)d_in[0];
    const float* vfea = (const float*)d_in[1];
    const int*   inv  = (const int*)d_in[2];
    const int*   cil  = (const int*)d_in[3];
    const int*   cin  = (const int*)d_in[4];
    const float* W_in = (const float*)d_in[5];
    const float* b_in = (const float*)d_in[6];
    const float* W1   = (const float*)d_in[7];
    const float* b1   = (const float*)d_in[8];
    const float* g1   = (const float*)d_in[9];
    const float* be1  = (const float*)d_in[10];
    const float* W2   = (const float*)d_in[11];
    const float* b2   = (const float*)d_in[12];
    const float* g2   = (const float*)d_in[13];
    const float* be2  = (const float*)d_in[14];
    const float* W3   = (const float*)d_in[15];
    const float* b3   = (const float*)d_in[16];
    const float* Wo1  = (const float*)d_in[17];
    const float* bo1  = (const float*)d_in[18];
    const float* Wo2  = (const float*)d_in[19];
    const float* bo2  = (const float*)d_in[20];
    float* out = (float*)d_out;

    const int PTS_SMEM = 36352;
    cudaFuncSetAttribute(k_points, cudaFuncAttributeMaxDynamicSharedMemorySize, PTS_SMEM);

    k_zero<<<2048, 256>>>();
    k_prep<<<64, 256>>>(Wo1, Wo2, W_in);
    k_counts<<<(NPTS + 255) / 256, 256>>>(inv, cin);
    k_identity<<<NV / 64, 256>>>(feat, vfea, inv, b_in);
    k_mlp1<<<(ND + 127) / 128, 256>>>(W1, b1);
    k_mlp2<<<(ND + 127) / 128, 256>>>(g1, be1, W2, b2);
    k_mlp3<<<(ND + 127) / 128, 256>>>(g2, be2, W3, b3);
    k_points<<<NPTS / 128, 256, PTS_SMEM>>>(cil, cin, inv, bo1, bo2);
    k_gather<<<(NPTS * 32) / 256, 256>>>(cin, out);
}

// round 6
// speedup vs baseline: 1.5223x; 1.2612x over previous
#include <cuda_runtime.h>
#include <cuda_fp16.h>

#define NV   120000
#define ND   30000
#define NV2  60000
#define NPTS 400000
#define CD   128
#define HD   64

// ---------------- scratch (static device globals; no allocation) ----------------
__device__ float  g_ds[ND * CD];          // segment sums of x
__device__ float  g_cntd[ND];
__device__ __half g_idh[NV * CD];         // identity, f16
__device__ float  g_t1[ND * HD];
__device__ float  g_t2[ND * HD];
__device__ __half g_hmh[ND * CD];         // hm, f16
__device__ float  g_pfea[NV2 * CD];       // segment sums of pts
__device__ float  g_cntv2[NV2];
__device__ float  g_stats[512];
// fragment-layout weights: idx = ((c*4 + wn)*32 + lane)*8 + nf*2 + j
__device__ __align__(16) unsigned g_Wof1[16 * 4 * 32 * 8];   // Wo1 (K=256): 64KB
__device__ __align__(16) unsigned g_Wof2[8 * 4 * 32 * 8];    // Wo2 (K=128): 32KB
__device__ __align__(16) unsigned g_Wofin[8 * 4 * 32 * 8];   // W_in (K=128): 32KB

__device__ __forceinline__ float lrelu(float x) { return x > 0.f ? x : 0.1f * x; }

__device__ __forceinline__ void red_add_v4(float* p, float4 v) {
    asm volatile("red.global.add.v4.f32 [%0], {%1,%2,%3,%4};"
                 :: "l"(p), "f"(v.x), "f"(v.y), "f"(v.z), "f"(v.w) : "memory");
}
__device__ __forceinline__ void red_add_v2(float* p, float a, float b) {
    asm volatile("red.global.add.v2.f32 [%0], {%1,%2};"
                 :: "l"(p), "f"(a), "f"(b) : "memory");
}
__device__ __forceinline__ void mma16816(float* c, const unsigned* a, const unsigned* b) {
    asm volatile("mma.sync.aligned.m16n8k16.row.col.f32.f16.f16.f32 "
                 "{%0,%1,%2,%3},{%4,%5,%6,%7},{%8,%9},{%0,%1,%2,%3};"
                 : "+f"(c[0]), "+f"(c[1]), "+f"(c[2]), "+f"(c[3])
                 : "r"(a[0]), "r"(a[1]), "r"(a[2]), "r"(a[3]), "r"(b[0]), "r"(b[1]));
}
__device__ __forceinline__ void ldsm4(unsigned* r, unsigned addr) {
    asm volatile("ldmatrix.sync.aligned.m8n8.x4.shared.b16 {%0,%1,%2,%3}, [%4];"
                 : "=r"(r[0]), "=r"(r[1]), "=r"(r[2]), "=r"(r[3]) : "r"(addr));
}
__device__ __forceinline__ void cp16(unsigned saddr, const void* gptr) {
    asm volatile("cp.async.cg.shared.global [%0], [%1], 16;" :: "r"(saddr), "l"(gptr) : "memory");
}

// ---------------- zero scratch ----------------
__global__ void k_zero() {
    int idx = blockIdx.x * blockDim.x + threadIdx.x;
    int stride = gridDim.x * blockDim.x;
    for (int i = idx; i < ND * CD; i += stride)  g_ds[i] = 0.f;
    for (int i = idx; i < ND; i += stride)       g_cntd[i] = 0.f;
    for (int i = idx; i < NV2 * CD; i += stride) g_pfea[i] = 0.f;
    for (int i = idx; i < NV2; i += stride)      g_cntv2[i] = 0.f;
    for (int i = idx; i < 512; i += stride)      g_stats[i] = 0.f;
}

// ---------------- weight prep: fragment-order f16 weights ----------------
__global__ void k_prep(const float* __restrict__ Wo1, const float* __restrict__ Wo2,
                       const float* __restrict__ Win) {
    int i = blockIdx.x * blockDim.x + threadIdx.x;
    if (i < 16384) {
        int j = i & 1, nf = (i >> 1) & 3, lane = (i >> 3) & 31, wn = (i >> 8) & 3, c = i >> 10;
        int n = wn * 32 + nf * 8 + (lane >> 2);
        int k = c * 16 + (lane & 3) * 2 + j * 8;
        __half2 h = __floats2half2_rn(Wo1[k * 128 + n], Wo1[(k + 1) * 128 + n]);
        g_Wof1[i] = *(unsigned*)&h;
    }
    if (i < 8192) {
        int j = i & 1, nf = (i >> 1) & 3, lane = (i >> 3) & 31, wn = (i >> 8) & 3, c = i >> 10;
        int n = wn * 32 + nf * 8 + (lane >> 2);
        int k = c * 16 + (lane & 3) * 2 + j * 8;
        __half2 ha = __floats2half2_rn(Wo2[k * 128 + n], Wo2[(k + 1) * 128 + n]);
        g_Wof2[i] = *(unsigned*)&ha;
        __half2 hb = __floats2half2_rn(Win[k * 128 + n], Win[(k + 1) * 128 + n]);
        g_Wofin[i] = *(unsigned*)&hb;
    }
}

// ---------------- segment counts ----------------
__global__ void k_counts(const int* __restrict__ inv, const int* __restrict__ cin) {
    int i = blockIdx.x * blockDim.x + threadIdx.x;
    if (i < NV)   atomicAdd(&g_cntd[inv[i]], 1.0f);
    if (i < NPTS) atomicAdd(&g_cntv2[cin[i]], 1.0f);
}

// ---------------- identity = lrelu((f+v) @ W_in + b_in) -> f16; warp-per-row I/O ----------------
__global__ void __launch_bounds__(256, 3) k_identity(
    const float* __restrict__ feat, const float* __restrict__ vfea,
    const int* __restrict__ inv, const float* __restrict__ bias) {
    __shared__ __half Asm[64][136];   // 17408 B

    const int tid  = threadIdx.x;
    const int lane = tid & 31;
    const int w    = tid >> 5;
    const int wm   = w & 1;
    const int wn   = w >> 1;
    const int g    = lane >> 2;
    const int tg   = lane & 3;
    const int lrow = lane & 15;
    const int lk8  = (lane >> 4) * 8;
    const int m0   = blockIdx.x * 64;
    const unsigned as_base = (unsigned)__cvta_generic_to_shared(&Asm[0][0]);

    // ---- load: warp per row (contiguous), red-add x to g_ds, f16 to SMEM ----
#pragma unroll
    for (int p = 0; p < 8; ++p) {
        int row  = p * 8 + w;
        int grow = m0 + row;
        int seg  = inv[grow];
        float4 f = *(const float4*)(feat + (size_t)grow * CD + lane * 4);
        float4 v = *(const float4*)(vfea + (size_t)grow * CD + lane * 4);
        float4 x = make_float4(f.x + v.x, f.y + v.y, f.z + v.z, f.w + v.w);
        red_add_v4(g_ds + (size_t)seg * CD + lane * 4, x);
        __half2 h0 = __floats2half2_rn(x.x, x.y);
        __half2 h1 = __floats2half2_rn(x.z, x.w);
        uint2 u; u.x = *(unsigned*)&h0; u.y = *(unsigned*)&h1;
        *(uint2*)&Asm[row][lane * 4] = u;
    }
    __syncthreads();

    float acc[2][4][4];
#pragma unroll
    for (int a = 0; a < 2; ++a)
#pragma unroll
        for (int b = 0; b < 4; ++b)
#pragma unroll
            for (int c = 0; c < 4; ++c) acc[a][b][c] = 0.f;

#pragma unroll
    for (int c = 0; c < 8; ++c) {
        unsigned af[2][4], bf[4][2];
#pragma unroll
        for (int mf = 0; mf < 2; ++mf)
            ldsm4(af[mf], as_base + ((wm * 32 + mf * 16 + lrow) * 136 + c * 16 + lk8) * 2);
        const uint4* wf = (const uint4*)(g_Wofin + (((c * 4 + wn) * 32 + lane) << 3));
        uint4 u0 = wf[0], u1 = wf[1];
        bf[0][0] = u0.x; bf[0][1] = u0.y; bf[1][0] = u0.z; bf[1][1] = u0.w;
        bf[2][0] = u1.x; bf[2][1] = u1.y; bf[3][0] = u1.z; bf[3][1] = u1.w;
#pragma unroll
        for (int mf = 0; mf < 2; ++mf)
#pragma unroll
            for (int nf = 0; nf < 4; ++nf)
                mma16816(acc[mf][nf], af[mf], bf[nf]);
    }
    __syncthreads();

    // epilogue: bias+lrelu -> f16 staged in Asm
#pragma unroll
    for (int mf = 0; mf < 2; ++mf) {
        int r0 = wm * 32 + mf * 16 + g;
#pragma unroll
        for (int nf = 0; nf < 4; ++nf) {
            int col = wn * 32 + nf * 8 + tg * 2;
            float b0 = bias[col], b1v = bias[col + 1];
            float* cc = acc[mf][nf];
            *(__half2*)&Asm[r0][col]     = __floats2half2_rn(lrelu(cc[0] + b0), lrelu(cc[1] + b1v));
            *(__half2*)&Asm[r0 + 8][col] = __floats2half2_rn(lrelu(cc[2] + b0), lrelu(cc[3] + b1v));
        }
    }
    __syncthreads();
    // store: warp per row (contiguous 256B)
#pragma unroll
    for (int p = 0; p < 8; ++p) {
        int row = p * 8 + w;
        *(uint2*)(g_idh + (size_t)(m0 + row) * CD + lane * 4) = *(const uint2*)&Asm[row][lane * 4];
    }
}

// ---------------- MLP stage 1: t1 = lrelu((ds/cnt) @ W1 + b1), stats ----------------
__global__ void __launch_bounds__(256) k_mlp1(const float* __restrict__ W, const float* __restrict__ bias) {
    __shared__ float As[2][8][128];
    __shared__ float Bs[2][8][64];
    __shared__ float ssum[64], ssq[64];
    const int tid = threadIdx.x;
    if (tid < 64) { ssum[tid] = 0.f; ssq[tid] = 0.f; }
    const int tx = tid & 7, ty = tid >> 3;
    const int m0 = blockIdx.x * 128;
    const int arow = tid >> 1, acol = (tid & 1) * 4;
    const int grow = m0 + arow;
    const bool rv = grow < ND;
    const float ic = rv ? 1.0f / fmaxf(g_cntd[grow], 1.0f) : 0.f;
    const int brow = tid >> 4, bcol = (tid & 15) * 4;

    float acc[4][8];
#pragma unroll
    for (int i = 0; i < 4; ++i)
#pragma unroll
        for (int j = 0; j < 8; ++j) acc[i][j] = 0.f;

    float4 aR = make_float4(0, 0, 0, 0), bR = make_float4(0, 0, 0, 0);
    if (rv) {
        float4 t = *(const float4*)(g_ds + (size_t)grow * CD + acol);
        aR = make_float4(t.x * ic, t.y * ic, t.z * ic, t.w * ic);
    }
    if (tid < 128) bR = *(const float4*)(W + brow * 64 + bcol);
    As[0][acol + 0][arow] = aR.x; As[0][acol + 1][arow] = aR.y;
    As[0][acol + 2][arow] = aR.z; As[0][acol + 3][arow] = aR.w;
    if (tid < 128) *(float4*)&Bs[0][brow][bcol] = bR;
    __syncthreads();

    for (int c = 0; c < 16; ++c) {
        const int cur = c & 1;
        if (c + 1 < 16) {
            if (rv) {
                float4 t = *(const float4*)(g_ds + (size_t)grow * CD + (c + 1) * 8 + acol);
                aR = make_float4(t.x * ic, t.y * ic, t.z * ic, t.w * ic);
            }
            if (tid < 128) bR = *(const float4*)(W + ((c + 1) * 8 + brow) * 64 + bcol);
        }
#pragma unroll
        for (int k = 0; k < 8; ++k) {
            float4 a = *(const float4*)&As[cur][k][ty * 4];
            float4 b0 = *(const float4*)&Bs[cur][k][tx * 8];
            float4 b1 = *(const float4*)&Bs[cur][k][tx * 8 + 4];
            float av[4] = {a.x, a.y, a.z, a.w};
            float bv[8] = {b0.x, b0.y, b0.z, b0.w, b1.x, b1.y, b1.z, b1.w};
#pragma unroll
            for (int i = 0; i < 4; ++i)
#pragma unroll
                for (int j = 0; j < 8; ++j)
                    acc[i][j] += av[i] * bv[j];
        }
        if (c + 1 < 16) {
            const int nb = cur ^ 1;
            As[nb][acol + 0][arow] = aR.x; As[nb][acol + 1][arow] = aR.y;
            As[nb][acol + 2][arow] = aR.z; As[nb][acol + 3][arow] = aR.w;
            if (tid < 128) *(float4*)&Bs[nb][brow][bcol] = bR;
        }
        __syncthreads();
    }

    float bb[8];
#pragma unroll
    for (int j = 0; j < 8; ++j) bb[j] = bias[tx * 8 + j];
    float cs[8], cq[8];
#pragma unroll
    for (int j = 0; j < 8; ++j) { cs[j] = 0.f; cq[j] = 0.f; }
#pragma unroll
    for (int i = 0; i < 4; ++i) {
        int r = m0 + ty * 4 + i;
        if (r < ND) {
            float o[8];
#pragma unroll
            for (int j = 0; j < 8; ++j) {
                o[j] = lrelu(acc[i][j] + bb[j]);
                cs[j] += o[j]; cq[j] += o[j] * o[j];
            }
            *(float4*)(g_t1 + (size_t)r * 64 + tx * 8)     = make_float4(o[0], o[1], o[2], o[3]);
            *(float4*)(g_t1 + (size_t)r * 64 + tx * 8 + 4) = make_float4(o[4], o[5], o[6], o[7]);
        }
    }
#pragma unroll
    for (int j = 0; j < 8; ++j) {
        atomicAdd(&ssum[tx * 8 + j], cs[j]);
        atomicAdd(&ssq[tx * 8 + j], cq[j]);
    }
    __syncthreads();
    if (tid < 64) {
        atomicAdd(&g_stats[tid], ssum[tid]);
        atomicAdd(&g_stats[128 + tid], ssq[tid]);
    }
}

// ---------------- MLP stage 2: t2 = lrelu(BN1(t1) @ W2 + b2), stats ----------------
__global__ void __launch_bounds__(256) k_mlp2(const float* __restrict__ gam, const float* __restrict__ bet,
                                              const float* __restrict__ W, const float* __restrict__ bias) {
    __shared__ float As[2][8][128];
    __shared__ float Bs[2][8][64];
    __shared__ float amul[64], aadd[64];
    __shared__ float ssum[64], ssq[64];
    const int tid = threadIdx.x;
    if (tid < 64) {
        const float im = 1.0f / (float)ND;
        float m = g_stats[tid] * im;
        float v = g_stats[128 + tid] * im - m * m;
        float gm = rsqrtf(v + 1e-5f) * gam[tid];
        amul[tid] = gm; aadd[tid] = bet[tid] - m * gm;
        ssum[tid] = 0.f; ssq[tid] = 0.f;
    }
    __syncthreads();
    const int tx = tid & 7, ty = tid >> 3;
    const int m0 = blockIdx.x * 128;
    const int arow = tid >> 1, acol = (tid & 1) * 4;
    const int grow = m0 + arow;
    const bool rv = grow < ND;
    const int brow = tid >> 4, bcol = (tid & 15) * 4;

    float acc[4][8];
#pragma unroll
    for (int i = 0; i < 4; ++i)
#pragma unroll
        for (int j = 0; j < 8; ++j) acc[i][j] = 0.f;

    float4 aR = make_float4(0, 0, 0, 0), bR = make_float4(0, 0, 0, 0);
    if (rv) {
        float4 t = *(const float4*)(g_t1 + (size_t)grow * 64 + acol);
        float4 mm = *(const float4*)&amul[acol];
        float4 ad = *(const float4*)&aadd[acol];
        aR = make_float4(t.x * mm.x + ad.x, t.y * mm.y + ad.y, t.z * mm.z + ad.z, t.w * mm.w + ad.w);
    }
    if (tid < 128) bR = *(const float4*)(W + brow * 64 + bcol);
    As[0][acol + 0][arow] = aR.x; As[0][acol + 1][arow] = aR.y;
    As[0][acol + 2][arow] = aR.z; As[0][acol + 3][arow] = aR.w;
    if (tid < 128) *(float4*)&Bs[0][brow][bcol] = bR;
    __syncthreads();

    for (int c = 0; c < 8; ++c) {
        const int cur = c & 1;
        if (c + 1 < 8) {
            if (rv) {
                int col = (c + 1) * 8 + acol;
                float4 t = *(const float4*)(g_t1 + (size_t)grow * 64 + col);
                float4 mm = *(const float4*)&amul[col];
                float4 ad = *(const float4*)&aadd[col];
                aR = make_float4(t.x * mm.x + ad.x, t.y * mm.y + ad.y, t.z * mm.z + ad.z, t.w * mm.w + ad.w);
            }
            if (tid < 128) bR = *(const float4*)(W + ((c + 1) * 8 + brow) * 64 + bcol);
        }
#pragma unroll
        for (int k = 0; k < 8; ++k) {
            float4 a = *(const float4*)&As[cur][k][ty * 4];
            float4 b0 = *(const float4*)&Bs[cur][k][tx * 8];
            float4 b1 = *(const float4*)&Bs[cur][k][tx * 8 + 4];
            float av[4] = {a.x, a.y, a.z, a.w};
            float bv[8] = {b0.x, b0.y, b0.z, b0.w, b1.x, b1.y, b1.z, b1.w};
#pragma unroll
            for (int i = 0; i < 4; ++i)
#pragma unroll
                for (int j = 0; j < 8; ++j)
                    acc[i][j] += av[i] * bv[j];
        }
        if (c + 1 < 8) {
            const int nb = cur ^ 1;
            As[nb][acol + 0][arow] = aR.x; As[nb][acol + 1][arow] = aR.y;
            As[nb][acol + 2][arow] = aR.z; As[nb][acol + 3][arow] = aR.w;
            if (tid < 128) *(float4*)&Bs[nb][brow][bcol] = bR;
        }
        __syncthreads();
    }

    float bb[8];
#pragma unroll
    for (int j = 0; j < 8; ++j) bb[j] = bias[tx * 8 + j];
    float cs[8], cq[8];
#pragma unroll
    for (int j = 0; j < 8; ++j) { cs[j] = 0.f; cq[j] = 0.f; }
#pragma unroll
    for (int i = 0; i < 4; ++i) {
        int r = m0 + ty * 4 + i;
        if (r < ND) {
            float o[8];
#pragma unroll
            for (int j = 0; j < 8; ++j) {
                o[j] = lrelu(acc[i][j] + bb[j]);
                cs[j] += o[j]; cq[j] += o[j] * o[j];
            }
            *(float4*)(g_t2 + (size_t)r * 64 + tx * 8)     = make_float4(o[0], o[1], o[2], o[3]);
            *(float4*)(g_t2 + (size_t)r * 64 + tx * 8 + 4) = make_float4(o[4], o[5], o[6], o[7]);
        }
    }
#pragma unroll
    for (int j = 0; j < 8; ++j) {
        atomicAdd(&ssum[tx * 8 + j], cs[j]);
        atomicAdd(&ssq[tx * 8 + j], cq[j]);
    }
    __syncthreads();
    if (tid < 64) {
        atomicAdd(&g_stats[256 + tid], ssum[tid]);
        atomicAdd(&g_stats[384 + tid], ssq[tid]);
    }
}

// ---------------- MLP stage 3: hm = lrelu(BN2(t2) @ W3 + b3) -> f16 ----------------
__global__ void __launch_bounds__(256) k_mlp3(const float* __restrict__ gam, const float* __restrict__ bet,
                                              const float* __restrict__ W, const float* __restrict__ bias) {
    __shared__ float As[2][8][128];
    __shared__ float Bs[2][8][128];
    __shared__ float amul[64], aadd[64];
    const int tid = threadIdx.x;
    if (tid < 64) {
        const float im = 1.0f / (float)ND;
        float m = g_stats[256 + tid] * im;
        float v = g_stats[384 + tid] * im - m * m;
        float gm = rsqrtf(v + 1e-5f) * gam[tid];
        amul[tid] = gm; aadd[tid] = bet[tid] - m * gm;
    }
    __syncthreads();
    const int tx = tid & 15, ty = tid >> 4;
    const int m0 = blockIdx.x * 128;
    const int arow = tid >> 1, acol = (tid & 1) * 4;
    const int grow = m0 + arow;
    const bool rv = grow < ND;
    const int brow = tid >> 5, bcol = (tid & 31) * 4;

    float acc[8][8];
#pragma unroll
    for (int i = 0; i < 8; ++i)
#pragma unroll
        for (int j = 0; j < 8; ++j) acc[i][j] = 0.f;

    float4 aR = make_float4(0, 0, 0, 0), bR;
    if (rv) {
        float4 t = *(const float4*)(g_t2 + (size_t)grow * 64 + acol);
        float4 mm = *(const float4*)&amul[acol];
        float4 ad = *(const float4*)&aadd[acol];
        aR = make_float4(t.x * mm.x + ad.x, t.y * mm.y + ad.y, t.z * mm.z + ad.z, t.w * mm.w + ad.w);
    }
    bR = *(const float4*)(W + brow * CD + bcol);
    As[0][acol + 0][arow] = aR.x; As[0][acol + 1][arow] = aR.y;
    As[0][acol + 2][arow] = aR.z; As[0][acol + 3][arow] = aR.w;
    *(float4*)&Bs[0][brow][bcol] = bR;
    __syncthreads();

    for (int c = 0; c < 8; ++c) {
        const int cur = c & 1;
        if (c + 1 < 8) {
            if (rv) {
                int col = (c + 1) * 8 + acol;
                float4 t = *(const float4*)(g_t2 + (size_t)grow * 64 + col);
                float4 mm = *(const float4*)&amul[col];
                float4 ad = *(const float4*)&aadd[col];
                aR = make_float4(t.x * mm.x + ad.x, t.y * mm.y + ad.y, t.z * mm.z + ad.z, t.w * mm.w + ad.w);
            } else aR = make_float4(0, 0, 0, 0);
            bR = *(const float4*)(W + ((c + 1) * 8 + brow) * CD + bcol);
        }
#pragma unroll
        for (int k = 0; k < 8; ++k) {
            float4 a0 = *(const float4*)&As[cur][k][ty * 8];
            float4 a1 = *(const float4*)&As[cur][k][ty * 8 + 4];
            float4 b0 = *(const float4*)&Bs[cur][k][tx * 8];
            float4 b1 = *(const float4*)&Bs[cur][k][tx * 8 + 4];
            float av[8] = {a0.x, a0.y, a0.z, a0.w, a1.x, a1.y, a1.z, a1.w};
            float bv[8] = {b0.x, b0.y, b0.z, b0.w, b1.x, b1.y, b1.z, b1.w};
#pragma unroll
            for (int i = 0; i < 8; ++i)
#pragma unroll
                for (int j = 0; j < 8; ++j)
                    acc[i][j] += av[i] * bv[j];
        }
        if (c + 1 < 8) {
            const int nb = cur ^ 1;
            As[nb][acol + 0][arow] = aR.x; As[nb][acol + 1][arow] = aR.y;
            As[nb][acol + 2][arow] = aR.z; As[nb][acol + 3][arow] = aR.w;
            *(float4*)&Bs[nb][brow][bcol] = bR;
        }
        __syncthreads();
    }

    float bb[8];
#pragma unroll
    for (int j = 0; j < 8; ++j) bb[j] = bias[tx * 8 + j];
#pragma unroll
    for (int i = 0; i < 8; ++i) {
        int r = m0 + ty * 8 + i;
        if (r < ND) {
            __half2 h[4];
#pragma unroll
            for (int j = 0; j < 4; ++j)
                h[j] = __floats2half2_rn(lrelu(acc[i][2 * j] + bb[2 * j]),
                                         lrelu(acc[i][2 * j + 1] + bb[2 * j + 1]));
            uint4 u;
            u.x = *(unsigned*)&h[0]; u.y = *(unsigned*)&h[1];
            u.z = *(unsigned*)&h[2]; u.w = *(unsigned*)&h[3];
            *(uint4*)(g_hmh + (size_t)r * CD + tx * 8) = u;
        }
    }
}

// ---------------- fused point path: cp.async double-buffered gather + ldmatrix + frag weights ----------------
__global__ void __launch_bounds__(256, 2) k_points(
    const int* __restrict__ cil, const int* __restrict__ cin, const int* __restrict__ inv,
    const float* __restrict__ bo1, const float* __restrict__ bo2) {
    extern __shared__ __align__(16) char smp[];
    __half (*At0)[136] = (__half (*)[136])smp;               // 34816 B
    __half (*At1)[136] = (__half (*)[136])(smp + 34816);     // 34816 B
    int* sv = (int*)(smp + 69632);
    int* sw = sv + 128;
    int* ss = sw + 128;                                      // total 71168 B

    const int tid  = threadIdx.x;
    const int lane = tid & 31;
    const int w    = tid >> 5;
    const int wm   = w & 1;
    const int wn   = w >> 1;
    const int g    = lane >> 2;
    const int tg   = lane & 3;
    const int lrow = lane & 15;
    const int lk8  = (lane >> 4) * 8;
    const int m0   = blockIdx.x * 128;   // NPTS % 128 == 0
    const unsigned a0_base = (unsigned)__cvta_generic_to_shared(&At0[0][0]);
    const unsigned a1_base = (unsigned)__cvta_generic_to_shared(&At1[0][0]);

    if (tid < 128) {
        int p = m0 + tid;
        int v = cil[p];
        sv[tid] = v;
        sw[tid] = inv[v];
        ss[tid] = cin[p];
    }
    __syncthreads();

    // ---- async gathers: 16 lanes cover one full 256B row per instruction ----
    {
        const int col = (tid & 15) * 8;          // halves
#pragma unroll
        for (int p2 = 0; p2 < 8; ++p2) {
            int row = (tid >> 4) + p2 * 16;
            cp16(a0_base + (row * 136 + col) * 2, g_idh + (size_t)sv[row] * CD + col);
        }
        asm volatile("cp.async.commit_group;" ::: "memory");
#pragma unroll
        for (int p2 = 0; p2 < 8; ++p2) {
            int row = (tid >> 4) + p2 * 16;
            cp16(a1_base + (row * 136 + col) * 2, g_hmh + (size_t)sw[row] * CD + col);
        }
        asm volatile("cp.async.commit_group;" ::: "memory");
    }

    float acc[4][4][4];
#pragma unroll
    for (int a = 0; a < 4; ++a)
#pragma unroll
        for (int b = 0; b < 4; ++b)
#pragma unroll
            for (int c = 0; c < 4; ++c) acc[a][b][c] = 0.f;

    asm volatile("cp.async.wait_group 1;" ::: "memory");
    __syncthreads();   // At0 (identity tile) ready

    // ---- stage 1a: chunks 0..7 on At0 ----
#pragma unroll
    for (int c = 0; c < 8; ++c) {
        unsigned af[4][4], bf[4][2];
#pragma unroll
        for (int mf = 0; mf < 4; ++mf)
            ldsm4(af[mf], a0_base + ((wm * 64 + mf * 16 + lrow) * 136 + c * 16 + lk8) * 2);
        const uint4* wf = (const uint4*)(g_Wof1 + (((c * 4 + wn) * 32 + lane) << 3));
        uint4 u0 = wf[0], u1 = wf[1];
        bf[0][0] = u0.x; bf[0][1] = u0.y; bf[1][0] = u0.z; bf[1][1] = u0.w;
        bf[2][0] = u1.x; bf[2][1] = u1.y; bf[3][0] = u1.z; bf[3][1] = u1.w;
#pragma unroll
        for (int mf = 0; mf < 4; ++mf)
#pragma unroll
            for (int nf = 0; nf < 4; ++nf)
                mma16816(acc[mf][nf], af[mf], bf[nf]);
    }

    asm volatile("cp.async.wait_group 0;" ::: "memory");
    __syncthreads();   // At1 (hm tile) ready; all warps done with At0

    // ---- stage 1b: chunks 8..15 on At1 ----
#pragma unroll
    for (int c = 0; c < 8; ++c) {
        unsigned af[4][4], bf[4][2];
#pragma unroll
        for (int mf = 0; mf < 4; ++mf)
            ldsm4(af[mf], a1_base + ((wm * 64 + mf * 16 + lrow) * 136 + c * 16 + lk8) * 2);
        const uint4* wf = (const uint4*)(g_Wof1 + ((((c + 8) * 4 + wn) * 32 + lane) << 3));
        uint4 u0 = wf[0], u1 = wf[1];
        bf[0][0] = u0.x; bf[0][1] = u0.y; bf[1][0] = u0.z; bf[1][1] = u0.w;
        bf[2][0] = u1.x; bf[2][1] = u1.y; bf[3][0] = u1.z; bf[3][1] = u1.w;
#pragma unroll
        for (int mf = 0; mf < 4; ++mf)
#pragma unroll
            for (int nf = 0; nf < 4; ++nf)
                mma16816(acc[mf][nf], af[mf], bf[nf]);
    }

    // ---- epilogue 1: H -> At0 (no one reads At0 anymore), reset acc ----
#pragma unroll
    for (int mf = 0; mf < 4; ++mf) {
        int r0 = wm * 64 + mf * 16 + g;
#pragma unroll
        for (int nf = 0; nf < 4; ++nf) {
            int col = wn * 32 + nf * 8 + tg * 2;
            float b0 = bo1[col], b1v = bo1[col + 1];
            float* cc = acc[mf][nf];
            *(__half2*)&At0[r0][col]     = __floats2half2_rn(lrelu(cc[0] + b0), lrelu(cc[1] + b1v));
            *(__half2*)&At0[r0 + 8][col] = __floats2half2_rn(lrelu(cc[2] + b0), lrelu(cc[3] + b1v));
            cc[0] = cc[1] = cc[2] = cc[3] = 0.f;
        }
    }
    __syncthreads();

    // ---- stage 2: K=128 on H (At0), B from g_Wof2 ----
#pragma unroll
    for (int c = 0; c < 8; ++c) {
        unsigned af[4][4], bf[4][2];
#pragma unroll
        for (int mf = 0; mf < 4; ++mf)
            ldsm4(af[mf], a0_base + ((wm * 64 + mf * 16 + lrow) * 136 + c * 16 + lk8) * 2);
        const uint4* wf = (const uint4*)(g_Wof2 + (((c * 4 + wn) * 32 + lane) << 3));
        uint4 u0 = wf[0], u1 = wf[1];
        bf[0][0] = u0.x; bf[0][1] = u0.y; bf[1][0] = u0.z; bf[1][1] = u0.w;
        bf[2][0] = u1.x; bf[2][1] = u1.y; bf[3][0] = u1.z; bf[3][1] = u1.w;
#pragma unroll
        for (int mf = 0; mf < 4; ++mf)
#pragma unroll
            for (int nf = 0; nf < 4; ++nf)
                mma16816(acc[mf][nf], af[mf], bf[nf]);
    }

    // ---- epilogue 2: Y -> segment sums (v2 reductions) ----
#pragma unroll
    for (int mf = 0; mf < 4; ++mf) {
        int r0 = wm * 64 + mf * 16 + g;
        int s0 = ss[r0], s1 = ss[r0 + 8];
#pragma unroll
        for (int nf = 0; nf < 4; ++nf) {
            int col = wn * 32 + nf * 8 + tg * 2;
            float b0 = bo2[col], b1v = bo2[col + 1];
            float* cc = acc[mf][nf];
            red_add_v2(g_pfea + (size_t)s0 * CD + col, cc[0] + b0, cc[1] + b1v);
            red_add_v2(g_pfea + (size_t)s1 * CD + col, cc[2] + b0, cc[3] + b1v);
        }
    }
}

// ---------------- out[p] = pfea_sum[cin[p]] / max(cnt,1) ----------------
__global__ void k_gather(const int* __restrict__ cin, float* __restrict__ out) {
    int idx = blockIdx.x * blockDim.x + threadIdx.x;
    if (idx >= NPTS * 32) return;
    int p = idx >> 5;
    int c = (idx & 31) * 4;
    int s = cin[p];
    float ic = 1.0f / fmaxf(g_cntv2[s], 1.0f);
    float4 v = *(const float4*)(g_pfea + (size_t)s * CD + c);
    *(float4*)(out + (size_t)p * CD + c) = make_float4(v.x * ic, v.y * ic, v.z * ic, v.w * ic);
}

// ---------------- launch ----------------
extern "C" void kernel_launch(void* const* d_in, const int* in_sizes, int n_in,
                              void* d_out, int out_size) {
    const float* feat = (const float*)d_in[0];
    const float* vfea = (const float*)d_in[1];
    const int*   inv  = (const int*)d_in[2];
    const int*   cil  = (const int*)d_in[3];
    const int*   cin  = (const int*)d_in[4];
    const float* W_in = (const float*)d_in[5];
    const float* b_in = (const float*)d_in[6];
    const float* W1   = (const float*)d_in[7];
    const float* b1   = (const float*)d_in[8];
    const float* g1   = (const float*)d_in[9];
    const float* be1  = (const float*)d_in[10];
    const float* W2   = (const float*)d_in[11];
    const float* b2   = (const float*)d_in[12];
    const float* g2   = (const float*)d_in[13];
    const float* be2  = (const float*)d_in[14];
    const float* W3   = (const float*)d_in[15];
    const float* b3   = (const float*)d_in[16];
    const float* Wo1  = (const float*)d_in[17];
    const float* bo1  = (const float*)d_in[18];
    const float* Wo2  = (const float*)d_in[19];
    const float* bo2  = (const float*)d_in[20];
    float* out = (float*)d_out;

    const int PTS_SMEM = 71168;
    cudaFuncSetAttribute(k_points, cudaFuncAttributeMaxDynamicSharedMemorySize, PTS_SMEM);

    k_zero<<<2048, 256>>>();
    k_prep<<<64, 256>>>(Wo1, Wo2, W_in);
    k_counts<<<(NPTS + 255) / 256, 256>>>(inv, cin);
    k_identity<<<NV / 64, 256>>>(feat, vfea, inv, b_in);
    k_mlp1<<<(ND + 127) / 128, 256>>>(W1, b1);
    k_mlp2<<<(ND + 127) / 128, 256>>>(g1, be1, W2, b2);
    k_mlp3<<<(ND + 127) / 128, 256>>>(g2, be2, W3, b3);
    k_points<<<NPTS / 128, 256, PTS_SMEM>>>(cil, cin, inv, bo1, bo2);
    k_gather<<<(NPTS * 32) / 256, 256>>>(cin, out);
}